// round 13
// baseline (speedup 1.0000x reference)
#include <cuda_runtime.h>
#include <cuda_bf16.h>
#include <cstdint>
#include <math.h>

#define Bb 2
#define Tt 2048
#define Ee 1024
#define Hh 16
#define Dd 64
#define Nn (Bb*Tt)      /* 4096 rows */
#define FF 4096
#define LN_EPS 1e-5f

// ======================= scratch (__device__ globals) =======================
__device__ float g_x1[Nn*Ee];

// bf16 split weights, transposed to [M_out][K] (K-major rows)
__device__ __nv_bfloat16 g_wqh[Ee*Ee], g_wql[Ee*Ee];
__device__ __nv_bfloat16 g_wkh[Ee*Ee], g_wkl[Ee*Ee];
__device__ __nv_bfloat16 g_wvh[Ee*Ee], g_wvl[Ee*Ee];
__device__ __nv_bfloat16 g_woh[Ee*Ee], g_wol[Ee*Ee];
__device__ __nv_bfloat16 g_w1h[(size_t)Ee*FF], g_w1l[(size_t)Ee*FF];
__device__ __nv_bfloat16 g_w2h[(size_t)FF*Ee], g_w2l[(size_t)FF*Ee];
// bf16 split activations
__device__ __nv_bfloat16 g_ah[(size_t)Nn*FF], g_al[(size_t)Nn*FF]; // LN1 out, later FF out
__device__ __nv_bfloat16 g_qh[Nn*Ee],  g_ql[Nn*Ee];
__device__ __nv_bfloat16 g_kh[Nn*Ee],  g_kl[Nn*Ee];
__device__ __nv_bfloat16 g_vh[Nn*Ee],  g_vl[Nn*Ee];
__device__ __nv_bfloat16 g_vth[Nn*Ee], g_vtl[Nn*Ee];   // V^T: [b,h][d][t]
__device__ __nv_bfloat16 g_atth[Nn*Ee], g_attl[Nn*Ee];
__device__ __nv_bfloat16 g_hh[Nn*Ee],  g_hl[Nn*Ee];    // LN2 out

// ======================= PTX helpers (baseline compute_103 only) ============
__device__ __forceinline__ uint32_t smem_to_u32(const void* p) {
    uint32_t a;
    asm("{ .reg .u64 t; cvta.to.shared.u64 t, %1; cvt.u32.u64 %0, t; }"
        : "=r"(a) : "l"(p));
    return a;
}
__device__ __forceinline__ void cp_async16(uint32_t dst, const void* src) {
    asm volatile("cp.async.cg.shared.global [%0], [%1], 16;"
                 :: "r"(dst), "l"(src) : "memory");
}
#define CP_COMMIT() asm volatile("cp.async.commit_group;" ::: "memory")
#define CP_WAIT(n)  asm volatile("cp.async.wait_group %0;" :: "n"(n) : "memory")

__device__ __forceinline__ void ldmx4(uint32_t& r0, uint32_t& r1,
                                      uint32_t& r2, uint32_t& r3, uint32_t a) {
    asm volatile("ldmatrix.sync.aligned.m8n8.x4.shared.b16 {%0,%1,%2,%3}, [%4];"
                 : "=r"(r0), "=r"(r1), "=r"(r2), "=r"(r3) : "r"(a));
}
__device__ __forceinline__ void mma16816(float* c, uint32_t a0, uint32_t a1,
                                         uint32_t a2, uint32_t a3,
                                         uint32_t b0, uint32_t b1) {
    asm volatile(
        "mma.sync.aligned.m16n8k16.row.col.f32.bf16.bf16.f32 "
        "{%0,%1,%2,%3}, {%4,%5,%6,%7}, {%8,%9}, {%0,%1,%2,%3};"
        : "+f"(c[0]), "+f"(c[1]), "+f"(c[2]), "+f"(c[3])
        : "r"(a0), "r"(a1), "r"(a2), "r"(a3), "r"(b0), "r"(b1));
}
__device__ __forceinline__ uint32_t pk2(float a, float b) {
    __nv_bfloat16 ha = __float2bfloat16(a), hb = __float2bfloat16(b);
    uint16_t ua = *(uint16_t*)&ha, ub = *(uint16_t*)&hb;
    return (uint32_t)ua | ((uint32_t)ub << 16);
}
__device__ __forceinline__ float blo(float a) {  // residual after bf16 round
    __nv_bfloat16 h = __float2bfloat16(a);
    return a - __bfloat162float(h);
}

// ======================= LayerNorm -> bf16 hi/lo ============================
__global__ __launch_bounds__(256) void ln_hl_kernel(
    const float* __restrict__ x, const float* __restrict__ gamma,
    const float* __restrict__ beta, __nv_bfloat16* __restrict__ hi,
    __nv_bfloat16* __restrict__ lo)
{
    int row = blockIdx.x;
    int tid = threadIdx.x;
    const float4* xp = (const float4*)(x + (size_t)row * Ee);
    float4 v = xp[tid];
    float s  = v.x + v.y + v.z + v.w;
    float sq = v.x*v.x + v.y*v.y + v.z*v.z + v.w*v.w;
    #pragma unroll
    for (int m = 16; m >= 1; m >>= 1) {
        s  += __shfl_xor_sync(0xffffffffu, s,  m);
        sq += __shfl_xor_sync(0xffffffffu, sq, m);
    }
    __shared__ float sh[16];
    int w = tid >> 5, l = tid & 31;
    if (l == 0) { sh[w] = s; sh[8 + w] = sq; }
    __syncthreads();
    if (tid < 32) {
        s  = (l < 8) ? sh[l]     : 0.f;
        sq = (l < 8) ? sh[8 + l] : 0.f;
        #pragma unroll
        for (int m = 4; m >= 1; m >>= 1) {
            s  += __shfl_xor_sync(0xffffffffu, s,  m);
            sq += __shfl_xor_sync(0xffffffffu, sq, m);
        }
        if (l == 0) { sh[0] = s; sh[8] = sq; }
    }
    __syncthreads();
    float mu  = sh[0] * (1.0f/Ee);
    float var = sh[8] * (1.0f/Ee) - mu*mu;
    float inv = rsqrtf(var + LN_EPS);
    float4 gv = ((const float4*)gamma)[tid];
    float4 bv = ((const float4*)beta)[tid];
    float f[4];
    f[0] = (v.x - mu)*inv*gv.x + bv.x;
    f[1] = (v.y - mu)*inv*gv.y + bv.y;
    f[2] = (v.z - mu)*inv*gv.z + bv.z;
    f[3] = (v.w - mu)*inv*gv.w + bv.w;
    __nv_bfloat16 hv[4], lv[4];
    #pragma unroll
    for (int j = 0; j < 4; j++) {
        hv[j] = __float2bfloat16(f[j]);
        lv[j] = __float2bfloat16(f[j] - __bfloat162float(hv[j]));
    }
    size_t o = (size_t)row * Ee + tid * 4;
    *(uint2*)(hi + o) = *(const uint2*)hv;
    *(uint2*)(lo + o) = *(const uint2*)lv;
}

// ====== W[K][M] f32 -> Wt_hi/lo[M][K] bf16 (transpose + split, scaled) ======
__global__ __launch_bounds__(256) void convT_hl_kernel(
    const float* __restrict__ W, __nv_bfloat16* __restrict__ th,
    __nv_bfloat16* __restrict__ tl, int K, int M, float scale)
{
    __shared__ float t[32][33];
    int m0 = blockIdx.x * 32, k0 = blockIdx.y * 32;
    int tx = threadIdx.x, ty = threadIdx.y;   // (32, 8)
    #pragma unroll
    for (int j = 0; j < 4; j++)
        t[ty + j*8][tx] = W[(size_t)(k0 + ty + j*8) * M + m0 + tx];
    __syncthreads();
    #pragma unroll
    for (int j = 0; j < 4; j++) {
        int ml = ty + j*8;
        float f = t[tx][ml] * scale;
        __nv_bfloat16 hv = __float2bfloat16(f);
        __nv_bfloat16 lv = __float2bfloat16(f - __bfloat162float(hv));
        size_t o = (size_t)(m0 + ml) * K + k0 + tx;
        th[o] = hv;
        tl[o] = lv;
    }
}

// ====== V [t][E] hi/lo -> V^T [b,h][d][t] hi/lo =============================
__global__ __launch_bounds__(256) void vtrans_kernel(
    const __nv_bfloat16* __restrict__ vh, const __nv_bfloat16* __restrict__ vl,
    __nv_bfloat16* __restrict__ vth, __nv_bfloat16* __restrict__ vtl)
{
    __shared__ __nv_bfloat16 s[64][72];
    int tc = blockIdx.x, h = blockIdx.y, b = blockIdx.z;
    int tid = threadIdx.x;
    #pragma unroll
    for (int pass = 0; pass < 2; pass++) {
        const __nv_bfloat16* src = pass ? vl : vh;
        __nv_bfloat16* dst = pass ? vtl : vth;
        #pragma unroll
        for (int it = 0; it < 16; it++) {
            int idx = tid + it * 256;
            int r = idx >> 6, d = idx & 63;
            s[r][d] = src[(size_t)(b*Tt + tc*64 + r) * Ee + h*64 + d];
        }
        __syncthreads();
        #pragma unroll
        for (int it = 0; it < 16; it++) {
            int idx = tid + it * 256;
            int d = idx >> 6, c = idx & 63;
            dst[((size_t)(b*Hh + h)*64 + d) * Tt + tc*64 + c] = s[c][d];
        }
        __syncthreads();
    }
}

// ======================= HMMA split-bf16 GEMM (64x64 warp tiles) ============
// C[N][M] = A[N][K] @ W[K][M]; A hi/lo bf16 [N][K], W hi/lo bf16 [M][K].
// 128x128x32 block tile, 128 thr (4 warps 2x2, each 64x64), 2-stage cp.async.
#define T_AH 0
#define T_AL 10240
#define T_BH 20480
#define T_BL 30720
#define STAGE_B 40960
#define HG_SMEM (2 * STAGE_B)

template<int RELU, int BIAS, int RES, int OUTHL>
__global__ __launch_bounds__(128, 2) void hgemm_kernel(
    const __nv_bfloat16* __restrict__ Ah, const __nv_bfloat16* __restrict__ Al,
    const __nv_bfloat16* __restrict__ Bh, const __nv_bfloat16* __restrict__ Bl,
    const float* __restrict__ bias, const float* __restrict__ res,
    float* __restrict__ C, __nv_bfloat16* __restrict__ Chi,
    __nv_bfloat16* __restrict__ Clo, int K, int M)
{
    extern __shared__ char smem[];
    const uint32_t sb = smem_to_u32(smem);
    const int tid = threadIdx.x;
    const int wid = tid >> 5, lid = tid & 31;
    const int wr = wid >> 1, wc = wid & 1;      // warp tile: rows wr*64, cols wc*64
    const int row0 = blockIdx.y * 128, col0 = blockIdx.x * 128;

    const __nv_bfloat16* src[4] = {
        Ah + (size_t)row0 * K, Al + (size_t)row0 * K,
        Bh + (size_t)col0 * K, Bl + (size_t)col0 * K };

    const uint32_t mrow = (uint32_t)(lid & 15);
    const uint32_t mcol = (uint32_t)(lid >> 4);
    const uint32_t aLane = (uint32_t)((wr * 64 + mrow) * 80 + mcol * 16);
    const uint32_t bLane = (uint32_t)((wc * 64 + mrow) * 80 + mcol * 16);

    float acc[4][8][4] = {};
    const int nchunk = K >> 5;

    // 128 threads: each thread loads one row (tid) x 4 segs of 16B per tensor
    auto issue = [&](int c, int stg) {
        const size_t k0 = (size_t)c * 32;
        #pragma unroll
        for (int t = 0; t < 4; t++) {
            const __nv_bfloat16* s = src[t] + k0 + (size_t)tid * K;
            uint32_t dst = sb + stg * STAGE_B + t * 10240 + (uint32_t)(tid * 80);
            #pragma unroll
            for (int sg = 0; sg < 4; sg++)
                cp_async16(dst + sg * 16, s + sg * 8);
        }
        CP_COMMIT();
    };

    issue(0, 0);
    for (int c = 0; c < nchunk; c++) {
        if (c + 1 < nchunk) {
            issue(c + 1, (c + 1) & 1);
            CP_WAIT(1);
        } else {
            CP_WAIT(0);
        }
        __syncthreads();

        const uint32_t st = sb + (uint32_t)((c & 1) * STAGE_B);
        #pragma unroll
        for (int kk = 0; kk < 2; kk++) {
            const uint32_t ko = (uint32_t)(kk * 32);
            uint32_t ah[4][4], al[4][4], bh[4][4], bl[4][4];
            #pragma unroll
            for (int mi = 0; mi < 4; mi++) {
                ldmx4(ah[mi][0], ah[mi][1], ah[mi][2], ah[mi][3],
                      st + T_AH + aLane + (uint32_t)(mi * 1280) + ko);
                ldmx4(al[mi][0], al[mi][1], al[mi][2], al[mi][3],
                      st + T_AL + aLane + (uint32_t)(mi * 1280) + ko);
            }
            #pragma unroll
            for (int np = 0; np < 4; np++) {
                ldmx4(bh[np][0], bh[np][1], bh[np][2], bh[np][3],
                      st + T_BH + bLane + (uint32_t)(np * 1280) + ko);
                ldmx4(bl[np][0], bl[np][1], bl[np][2], bl[np][3],
                      st + T_BL + bLane + (uint32_t)(np * 1280) + ko);
            }
            #pragma unroll
            for (int mi = 0; mi < 4; mi++) {
                #pragma unroll
                for (int nj = 0; nj < 8; nj++) {
                    uint32_t h0 = bh[nj >> 1][nj & 1], h1 = bh[nj >> 1][(nj & 1) + 2];
                    uint32_t l0 = bl[nj >> 1][nj & 1], l1 = bl[nj >> 1][(nj & 1) + 2];
                    float* cc = acc[mi][nj];
                    mma16816(cc, ah[mi][0], ah[mi][1], ah[mi][2], ah[mi][3], h0, h1);
                    mma16816(cc, ah[mi][0], ah[mi][1], ah[mi][2], ah[mi][3], l0, l1);
                    mma16816(cc, al[mi][0], al[mi][1], al[mi][2], al[mi][3], h0, h1);
                }
            }
        }
        __syncthreads();
    }

    // epilogue
    const int l4 = lid >> 2, l2 = (lid & 3) * 2;
    #pragma unroll
    for (int mi = 0; mi < 4; mi++) {
        const int r = row0 + wr * 64 + mi * 16 + l4;
        #pragma unroll
        for (int nj = 0; nj < 8; nj++) {
            const int cgl = col0 + wc * 64 + nj * 8 + l2;
            float b0 = 0.f, b1 = 0.f;
            if (BIAS) { b0 = bias[cgl]; b1 = bias[cgl + 1]; }
            float v0 = acc[mi][nj][0] + b0, v1 = acc[mi][nj][1] + b1;
            float v2 = acc[mi][nj][2] + b0, v3 = acc[mi][nj][3] + b1;
            if (RELU) {
                v0 = fmaxf(v0, 0.f); v1 = fmaxf(v1, 0.f);
                v2 = fmaxf(v2, 0.f); v3 = fmaxf(v3, 0.f);
            }
            if (RES) {
                const float* r0p = res + (size_t)r * M + cgl;
                const float* r1p = res + (size_t)(r + 8) * M + cgl;
                v0 += r0p[0]; v1 += r0p[1];
                v2 += r1p[0]; v3 += r1p[1];
            }
            if (OUTHL) {
                *(uint32_t*)(Chi + (size_t)r * M + cgl)       = pk2(v0, v1);
                *(uint32_t*)(Clo + (size_t)r * M + cgl)       = pk2(blo(v0), blo(v1));
                *(uint32_t*)(Chi + (size_t)(r + 8) * M + cgl) = pk2(v2, v3);
                *(uint32_t*)(Clo + (size_t)(r + 8) * M + cgl) = pk2(blo(v2), blo(v3));
            } else {
                float2 o0 = {v0, v1}, o1 = {v2, v3};
                *(float2*)(C + (size_t)r * M + cgl) = o0;
                *(float2*)(C + (size_t)(r + 8) * M + cgl) = o1;
            }
        }
    }
}

// ======================= HMMA flash attention (split bf16) ==================
// BQ=64, BK=64, D=64, 128 threads (4 warps, each 16 q-rows).
// smem tiles row stride 72 bf16 (144B, conflict-free ldmatrix). Q/K/V hi+lo.
#define FQH 0
#define FQL 9216
#define FKH 18432
#define FKL 27648
#define FVH 36864
#define FVL 46080
#define FL_SMEM 55296

__global__ __launch_bounds__(128) void flash_mma_kernel(
    const __nv_bfloat16* __restrict__ qh, const __nv_bfloat16* __restrict__ ql,
    const __nv_bfloat16* __restrict__ kh, const __nv_bfloat16* __restrict__ kl,
    const __nv_bfloat16* __restrict__ vth, const __nv_bfloat16* __restrict__ vtl,
    __nv_bfloat16* __restrict__ atth, __nv_bfloat16* __restrict__ attl)
{
    extern __shared__ char smf[];
    const uint32_t sb = smem_to_u32(smf);
    const int qt = blockIdx.x, h = blockIdx.y, b = blockIdx.z;
    const int tid = threadIdx.x, wid = tid >> 5, lid = tid & 31;

    const int lr = tid >> 1, lcb = (tid & 1) * 4;
    auto ldtile = [&](uint32_t off, const __nv_bfloat16* g, int gs) {
        #pragma unroll
        for (int i = 0; i < 4; i++)
            cp_async16(sb + off + (uint32_t)(lr * 144 + (lcb + i) * 16),
                       g + (size_t)lr * gs + (lcb + i) * 8);
    };

    const __nv_bfloat16* qsh = qh + ((size_t)(b*Tt + qt*64)) * Ee + h*64;
    const __nv_bfloat16* qsl = ql + ((size_t)(b*Tt + qt*64)) * Ee + h*64;
    const __nv_bfloat16* vbh = vth + ((size_t)(b*Hh + h) * 64) * Tt;
    const __nv_bfloat16* vbl = vtl + ((size_t)(b*Hh + h) * 64) * Tt;

    ldtile(FQH, qsh, Ee); ldtile(FQL, qsl, Ee);
    ldtile(FKH, kh + ((size_t)(b*Tt)) * Ee + h*64, Ee);
    ldtile(FKL, kl + ((size_t)(b*Tt)) * Ee + h*64, Ee);
    ldtile(FVH, vbh, Tt); ldtile(FVL, vbl, Tt);
    CP_COMMIT(); CP_WAIT(0);
    __syncthreads();

    const uint32_t arow = (uint32_t)(wid * 16 + (lid & 15));
    const uint32_t fcol = (uint32_t)((lid >> 4) * 16);
    uint32_t qfh[4][4], qfl[4][4];
    #pragma unroll
    for (int c = 0; c < 4; c++) {
        ldmx4(qfh[c][0], qfh[c][1], qfh[c][2], qfh[c][3],
              sb + FQH + arow * 144 + (uint32_t)(c * 32) + fcol);
        ldmx4(qfl[c][0], qfl[c][1], qfl[c][2], qfl[c][3],
              sb + FQL + arow * 144 + (uint32_t)(c * 32) + fcol);
    }

    const uint32_t brow = (uint32_t)(lid & 15);
    float oacc[8][4] = {};
    float m0 = -INFINITY, m1 = -INFINITY, l0 = 0.f, l1 = 0.f;

    const int rl0 = wid * 16 + (lid >> 2);
    const int cl0 = (lid & 3) * 2;

    for (int kt = 0; kt <= qt; kt++) {
        float sacc[8][4] = {};
        #pragma unroll
        for (int c = 0; c < 4; c++) {
            uint32_t bh_[4][4], bl_[4][4];
            #pragma unroll
            for (int np = 0; np < 4; np++) {
                ldmx4(bh_[np][0], bh_[np][1], bh_[np][2], bh_[np][3],
                      sb + FKH + (uint32_t)((np*16 + brow) * 144 + c*32) + fcol);
                ldmx4(bl_[np][0], bl_[np][1], bl_[np][2], bl_[np][3],
                      sb + FKL + (uint32_t)((np*16 + brow) * 144 + c*32) + fcol);
            }
            #pragma unroll
            for (int np = 0; np < 4; np++) {
                #pragma unroll
                for (int hf = 0; hf < 2; hf++) {
                    uint32_t H0 = bh_[np][hf], H1 = bh_[np][hf + 2];
                    uint32_t L0 = bl_[np][hf], L1 = bl_[np][hf + 2];
                    float* cc = sacc[2*np + hf];
                    mma16816(cc, qfh[c][0], qfh[c][1], qfh[c][2], qfh[c][3], H0, H1);
                    mma16816(cc, qfh[c][0], qfh[c][1], qfh[c][2], qfh[c][3], L0, L1);
                    mma16816(cc, qfl[c][0], qfl[c][1], qfl[c][2], qfl[c][3], H0, H1);
                }
            }
        }

        if (kt == qt) {
            #pragma unroll
            for (int j = 0; j < 8; j++) {
                int cb = j * 8 + cl0;
                #pragma unroll
                for (int e = 0; e < 4; e++) {
                    int cc = cb + (e & 1);
                    int rr = rl0 + ((e >= 2) ? 8 : 0);
                    if (cc > rr) sacc[j][e] = -INFINITY;
                }
            }
        }

        float mx0 = -INFINITY, mx1 = -INFINITY;
        #pragma unroll
        for (int j = 0; j < 8; j++) {
            mx0 = fmaxf(mx0, fmaxf(sacc[j][0], sacc[j][1]));
            mx1 = fmaxf(mx1, fmaxf(sacc[j][2], sacc[j][3]));
        }
        mx0 = fmaxf(mx0, __shfl_xor_sync(0xffffffffu, mx0, 1));
        mx0 = fmaxf(mx0, __shfl_xor_sync(0xffffffffu, mx0, 2));
        mx1 = fmaxf(mx1, __shfl_xor_sync(0xffffffffu, mx1, 1));
        mx1 = fmaxf(mx1, __shfl_xor_sync(0xffffffffu, mx1, 2));
        float mn0 = fmaxf(m0, mx0), mn1 = fmaxf(m1, mx1);
        float cr0 = __expf(m0 - mn0), cr1 = __expf(m1 - mn1);
        m0 = mn0; m1 = mn1;
        float s0 = 0.f, s1 = 0.f;
        #pragma unroll
        for (int j = 0; j < 8; j++) {
            sacc[j][0] = __expf(sacc[j][0] - mn0);
            sacc[j][1] = __expf(sacc[j][1] - mn0);
            sacc[j][2] = __expf(sacc[j][2] - mn1);
            sacc[j][3] = __expf(sacc[j][3] - mn1);
            s0 += sacc[j][0] + sacc[j][1];
            s1 += sacc[j][2] + sacc[j][3];
        }
        s0 += __shfl_xor_sync(0xffffffffu, s0, 1);
        s0 += __shfl_xor_sync(0xffffffffu, s0, 2);
        s1 += __shfl_xor_sync(0xffffffffu, s1, 1);
        s1 += __shfl_xor_sync(0xffffffffu, s1, 2);
        l0 = l0 * cr0 + s0;
        l1 = l1 * cr1 + s1;
        #pragma unroll
        for (int j = 0; j < 8; j++) {
            oacc[j][0] *= cr0; oacc[j][1] *= cr0;
            oacc[j][2] *= cr1; oacc[j][3] *= cr1;
        }

        uint32_t pfh[4][4], pfl[4][4];
        #pragma unroll
        for (int kc = 0; kc < 4; kc++) {
            const float* pa = sacc[2*kc];
            const float* pb = sacc[2*kc + 1];
            pfh[kc][0] = pk2(pa[0], pa[1]);
            pfh[kc][1] = pk2(pa[2], pa[3]);
            pfh[kc][2] = pk2(pb[0], pb[1]);
            pfh[kc][3] = pk2(pb[2], pb[3]);
            pfl[kc][0] = pk2(blo(pa[0]), blo(pa[1]));
            pfl[kc][1] = pk2(blo(pa[2]), blo(pa[3]));
            pfl[kc][2] = pk2(blo(pb[0]), blo(pb[1]));
            pfl[kc][3] = pk2(blo(pb[2]), blo(pb[3]));
        }

        #pragma unroll
        for (int kc = 0; kc < 4; kc++) {
            uint32_t vh_[4][4], vl_[4][4];
            #pragma unroll
            for (int np = 0; np < 4; np++) {
                ldmx4(vh_[np][0], vh_[np][1], vh_[np][2], vh_[np][3],
                      sb + FVH + (uint32_t)((np*16 + brow) * 144 + kc*32) + fcol);
                ldmx4(vl_[np][0], vl_[np][1], vl_[np][2], vl_[np][3],
                      sb + FVL + (uint32_t)((np*16 + brow) * 144 + kc*32) + fcol);
            }
            #pragma unroll
            for (int np = 0; np < 4; np++) {
                #pragma unroll
                for (int hf = 0; hf < 2; hf++) {
                    uint32_t H0 = vh_[np][hf], H1 = vh_[np][hf + 2];
                    uint32_t L0 = vl_[np][hf], L1 = vl_[np][hf + 2];
                    float* cc = oacc[2*np + hf];
                    mma16816(cc, pfh[kc][0], pfh[kc][1], pfh[kc][2], pfh[kc][3], H0, H1);
                    mma16816(cc, pfh[kc][0], pfh[kc][1], pfh[kc][2], pfh[kc][3], L0, L1);
                    mma16816(cc, pfl[kc][0], pfl[kc][1], pfl[kc][2], pfl[kc][3], H0, H1);
                }
            }
        }

        if (kt < qt) {
            __syncthreads();
            ldtile(FKH, kh + ((size_t)(b*Tt + (kt+1)*64)) * Ee + h*64, Ee);
            ldtile(FKL, kl + ((size_t)(b*Tt + (kt+1)*64)) * Ee + h*64, Ee);
            ldtile(FVH, vbh + (kt+1)*64, Tt);
            ldtile(FVL, vbl + (kt+1)*64, Tt);
            CP_COMMIT(); CP_WAIT(0);
            __syncthreads();
        }
    }

    float i0 = 1.f / l0, i1 = 1.f / l1;
    const size_t r0 = (size_t)(b*Tt + qt*64 + rl0);
    #pragma unroll
    for (int j = 0; j < 8; j++) {
        int d0 = h*64 + j*8 + cl0;
        float o0 = oacc[j][0] * i0, o1 = oacc[j][1] * i0;
        float o2 = oacc[j][2] * i1, o3 = oacc[j][3] * i1;
        *(uint32_t*)(atth + r0 * Ee + d0)       = pk2(o0, o1);
        *(uint32_t*)(attl + r0 * Ee + d0)       = pk2(blo(o0), blo(o1));
        *(uint32_t*)(atth + (r0 + 8) * Ee + d0) = pk2(o2, o3);
        *(uint32_t*)(attl + (r0 + 8) * Ee + d0) = pk2(blo(o2), blo(o3));
    }
}

// ======================= orchestration ======================================
extern "C" void kernel_launch(void* const* d_in, const int* in_sizes, int n_in,
                              void* d_out, int out_size)
{
    (void)in_sizes; (void)n_in; (void)out_size;
    const float* x     = (const float*)d_in[0];
    const float* ln1_g = (const float*)d_in[1];
    const float* ln1_b = (const float*)d_in[2];
    const float* Wq    = (const float*)d_in[3];
    const float* Wk    = (const float*)d_in[4];
    const float* Wv    = (const float*)d_in[5];
    const float* Wo    = (const float*)d_in[6];
    const float* bo    = (const float*)d_in[7];
    const float* ln2_g = (const float*)d_in[8];
    const float* ln2_b = (const float*)d_in[9];
    const float* W1    = (const float*)d_in[10];
    const float* b1    = (const float*)d_in[11];
    const float* W2    = (const float*)d_in[12];
    const float* b2    = (const float*)d_in[13];
    float* out = (float*)d_out;

    float* x1;
    cudaGetSymbolAddress((void**)&x1, g_x1);

    __nv_bfloat16 *wqh,*wql,*wkh,*wkl,*wvh,*wvl,*woh,*wol,*w1h,*w1l,*w2h,*w2l;
    __nv_bfloat16 *ah,*al,*qh,*ql,*kh,*kl,*vh,*vl,*vth,*vtl,*atth,*attl,*hh,*hl;
    cudaGetSymbolAddress((void**)&wqh, g_wqh); cudaGetSymbolAddress((void**)&wql, g_wql);
    cudaGetSymbolAddress((void**)&wkh, g_wkh); cudaGetSymbolAddress((void**)&wkl, g_wkl);
    cudaGetSymbolAddress((void**)&wvh, g_wvh); cudaGetSymbolAddress((void**)&wvl, g_wvl);
    cudaGetSymbolAddress((void**)&woh, g_woh); cudaGetSymbolAddress((void**)&wol, g_wol);
    cudaGetSymbolAddress((void**)&w1h, g_w1h); cudaGetSymbolAddress((void**)&w1l, g_w1l);
    cudaGetSymbolAddress((void**)&w2h, g_w2h); cudaGetSymbolAddress((void**)&w2l, g_w2l);
    cudaGetSymbolAddress((void**)&ah,  g_ah);  cudaGetSymbolAddress((void**)&al,  g_al);
    cudaGetSymbolAddress((void**)&qh,  g_qh);  cudaGetSymbolAddress((void**)&ql,  g_ql);
    cudaGetSymbolAddress((void**)&kh,  g_kh);  cudaGetSymbolAddress((void**)&kl,  g_kl);
    cudaGetSymbolAddress((void**)&vh,  g_vh);  cudaGetSymbolAddress((void**)&vl,  g_vl);
    cudaGetSymbolAddress((void**)&vth, g_vth); cudaGetSymbolAddress((void**)&vtl, g_vtl);
    cudaGetSymbolAddress((void**)&atth,g_atth);cudaGetSymbolAddress((void**)&attl,g_attl);
    cudaGetSymbolAddress((void**)&hh,  g_hh);  cudaGetSymbolAddress((void**)&hl,  g_hl);

    cudaFuncSetAttribute(hgemm_kernel<0,0,0,1>, cudaFuncAttributeMaxDynamicSharedMemorySize, HG_SMEM);
    cudaFuncSetAttribute(hgemm_kernel<1,1,0,1>, cudaFuncAttributeMaxDynamicSharedMemorySize, HG_SMEM);
    cudaFuncSetAttribute(hgemm_kernel<0,1,1,0>, cudaFuncAttributeMaxDynamicSharedMemorySize, HG_SMEM);
    cudaFuncSetAttribute(flash_mma_kernel, cudaFuncAttributeMaxDynamicSharedMemorySize, FL_SMEM);

    dim3 tb(32, 8);
    dim3 gE(8, 32);
    dim3 gF(32, 32);

    // weight conversions (Wq pre-scaled by 1/sqrt(D))
    convT_hl_kernel<<<dim3(32, 32),  tb>>>(Wq, wqh, wql, Ee, Ee, 0.125f);
    convT_hl_kernel<<<dim3(32, 32),  tb>>>(Wk, wkh, wkl, Ee, Ee, 1.f);
    convT_hl_kernel<<<dim3(32, 32),  tb>>>(Wv, wvh, wvl, Ee, Ee, 1.f);
    convT_hl_kernel<<<dim3(32, 32),  tb>>>(Wo, woh, wol, Ee, Ee, 1.f);
    convT_hl_kernel<<<dim3(128, 32), tb>>>(W1, w1h, w1l, Ee, FF, 1.f);
    convT_hl_kernel<<<dim3(32, 128), tb>>>(W2, w2h, w2l, FF, Ee, 1.f);

    // 1) LN1 -> bf16 hi/lo
    ln_hl_kernel<<<Nn, 256>>>(x, ln1_g, ln1_b, ah, al);
    // 2-4) q/k/v (bf16 hi/lo outputs)
    hgemm_kernel<0,0,0,1><<<gE, 128, HG_SMEM>>>(ah, al, wqh, wql, nullptr, nullptr, nullptr, qh, ql, Ee, Ee);
    hgemm_kernel<0,0,0,1><<<gE, 128, HG_SMEM>>>(ah, al, wkh, wkl, nullptr, nullptr, nullptr, kh, kl, Ee, Ee);
    hgemm_kernel<0,0,0,1><<<gE, 128, HG_SMEM>>>(ah, al, wvh, wvl, nullptr, nullptr, nullptr, vh, vl, Ee, Ee);
    // 5) V transpose + flash attention
    vtrans_kernel<<<dim3(Tt/64, Hh, Bb), 256>>>(vh, vl, vth, vtl);
    flash_mma_kernel<<<dim3(Tt/64, Hh, Bb), 128, FL_SMEM>>>(qh, ql, kh, kl, vth, vtl, atth, attl);
    // 6) x1 = x + att @ Wo + bo
    hgemm_kernel<0,1,1,0><<<gE, 128, HG_SMEM>>>(atth, attl, woh, wol, bo, x, x1, nullptr, nullptr, Ee, Ee);
    // 7) LN2 -> bf16 hi/lo
    ln_hl_kernel<<<Nn, 256>>>(x1, ln2_g, ln2_b, hh, hl);
    // 8) ff = relu(h @ W1 + b1)  (bf16 hi/lo output)
    hgemm_kernel<1,1,0,1><<<gF, 128, HG_SMEM>>>(hh, hl, w1h, w1l, b1, nullptr, nullptr, ah, al, Ee, FF);
    // 9) out = x1 + ff @ W2 + b2
    hgemm_kernel<0,1,1,0><<<gE, 128, HG_SMEM>>>(ah, al, w2h, w2l, b2, x1, out, nullptr, nullptr, FF, Ee);
}

// round 16
// speedup vs baseline: 1.1741x; 1.1741x over previous
#include <cuda_runtime.h>
#include <cuda_bf16.h>
#include <cstdint>
#include <math.h>

#define Bb 2
#define Tt 2048
#define Ee 1024
#define Hh 16
#define Dd 64
#define Nn (Bb*Tt)      /* 4096 rows */
#define FF 4096
#define LN_EPS 1e-5f

// ======================= scratch (__device__ globals) =======================
__device__ float g_x1[Nn*Ee];

// bf16 split weights, transposed to [M_out][K] (K-major rows)
__device__ __nv_bfloat16 g_wqh[Ee*Ee], g_wql[Ee*Ee];
__device__ __nv_bfloat16 g_wkh[Ee*Ee], g_wkl[Ee*Ee];
__device__ __nv_bfloat16 g_wvh[Ee*Ee], g_wvl[Ee*Ee];
__device__ __nv_bfloat16 g_woh[Ee*Ee], g_wol[Ee*Ee];
__device__ __nv_bfloat16 g_w1h[(size_t)Ee*FF], g_w1l[(size_t)Ee*FF];
__device__ __nv_bfloat16 g_w2h[(size_t)FF*Ee], g_w2l[(size_t)FF*Ee];
// bf16 split activations
__device__ __nv_bfloat16 g_ah[(size_t)Nn*FF], g_al[(size_t)Nn*FF]; // LN1 out, later FF out
__device__ __nv_bfloat16 g_qh[Nn*Ee],  g_ql[Nn*Ee];
__device__ __nv_bfloat16 g_kh[Nn*Ee],  g_kl[Nn*Ee];
__device__ __nv_bfloat16 g_vh[Nn*Ee],  g_vl[Nn*Ee];
__device__ __nv_bfloat16 g_vth[Nn*Ee], g_vtl[Nn*Ee];   // V^T: [b,h][d][t]
__device__ __nv_bfloat16 g_atth[Nn*Ee], g_attl[Nn*Ee];
__device__ __nv_bfloat16 g_hh[Nn*Ee],  g_hl[Nn*Ee];    // LN2 out

// ======================= PTX helpers (baseline compute_103 only) ============
__device__ __forceinline__ uint32_t smem_to_u32(const void* p) {
    uint32_t a;
    asm("{ .reg .u64 t; cvta.to.shared.u64 t, %1; cvt.u32.u64 %0, t; }"
        : "=r"(a) : "l"(p));
    return a;
}
__device__ __forceinline__ void cp_async16(uint32_t dst, const void* src) {
    asm volatile("cp.async.cg.shared.global [%0], [%1], 16;"
                 :: "r"(dst), "l"(src) : "memory");
}
#define CP_COMMIT() asm volatile("cp.async.commit_group;" ::: "memory")
#define CP_WAIT(n)  asm volatile("cp.async.wait_group %0;" :: "n"(n) : "memory")

__device__ __forceinline__ void ldmx4(uint32_t& r0, uint32_t& r1,
                                      uint32_t& r2, uint32_t& r3, uint32_t a) {
    asm volatile("ldmatrix.sync.aligned.m8n8.x4.shared.b16 {%0,%1,%2,%3}, [%4];"
                 : "=r"(r0), "=r"(r1), "=r"(r2), "=r"(r3) : "r"(a));
}
__device__ __forceinline__ void mma16816(float* c, uint32_t a0, uint32_t a1,
                                         uint32_t a2, uint32_t a3,
                                         uint32_t b0, uint32_t b1) {
    asm volatile(
        "mma.sync.aligned.m16n8k16.row.col.f32.bf16.bf16.f32 "
        "{%0,%1,%2,%3}, {%4,%5,%6,%7}, {%8,%9}, {%0,%1,%2,%3};"
        : "+f"(c[0]), "+f"(c[1]), "+f"(c[2]), "+f"(c[3])
        : "r"(a0), "r"(a1), "r"(a2), "r"(a3), "r"(b0), "r"(b1));
}
__device__ __forceinline__ uint32_t pk2(float a, float b) {
    __nv_bfloat16 ha = __float2bfloat16(a), hb = __float2bfloat16(b);
    uint16_t ua = *(uint16_t*)&ha, ub = *(uint16_t*)&hb;
    return (uint32_t)ua | ((uint32_t)ub << 16);
}
__device__ __forceinline__ float blo(float a) {  // residual after bf16 round
    __nv_bfloat16 h = __float2bfloat16(a);
    return a - __bfloat162float(h);
}

// ======================= LayerNorm -> bf16 hi/lo ============================
__global__ __launch_bounds__(256) void ln_hl_kernel(
    const float* __restrict__ x, const float* __restrict__ gamma,
    const float* __restrict__ beta, __nv_bfloat16* __restrict__ hi,
    __nv_bfloat16* __restrict__ lo)
{
    int row = blockIdx.x;
    int tid = threadIdx.x;
    const float4* xp = (const float4*)(x + (size_t)row * Ee);
    float4 v = xp[tid];
    float s  = v.x + v.y + v.z + v.w;
    float sq = v.x*v.x + v.y*v.y + v.z*v.z + v.w*v.w;
    #pragma unroll
    for (int m = 16; m >= 1; m >>= 1) {
        s  += __shfl_xor_sync(0xffffffffu, s,  m);
        sq += __shfl_xor_sync(0xffffffffu, sq, m);
    }
    __shared__ float sh[16];
    int w = tid >> 5, l = tid & 31;
    if (l == 0) { sh[w] = s; sh[8 + w] = sq; }
    __syncthreads();
    if (tid < 32) {
        s  = (l < 8) ? sh[l]     : 0.f;
        sq = (l < 8) ? sh[8 + l] : 0.f;
        #pragma unroll
        for (int m = 4; m >= 1; m >>= 1) {
            s  += __shfl_xor_sync(0xffffffffu, s,  m);
            sq += __shfl_xor_sync(0xffffffffu, sq, m);
        }
        if (l == 0) { sh[0] = s; sh[8] = sq; }
    }
    __syncthreads();
    float mu  = sh[0] * (1.0f/Ee);
    float var = sh[8] * (1.0f/Ee) - mu*mu;
    float inv = rsqrtf(var + LN_EPS);
    float4 gv = ((const float4*)gamma)[tid];
    float4 bv = ((const float4*)beta)[tid];
    float f[4];
    f[0] = (v.x - mu)*inv*gv.x + bv.x;
    f[1] = (v.y - mu)*inv*gv.y + bv.y;
    f[2] = (v.z - mu)*inv*gv.z + bv.z;
    f[3] = (v.w - mu)*inv*gv.w + bv.w;
    __nv_bfloat16 hv[4], lv[4];
    #pragma unroll
    for (int j = 0; j < 4; j++) {
        hv[j] = __float2bfloat16(f[j]);
        lv[j] = __float2bfloat16(f[j] - __bfloat162float(hv[j]));
    }
    size_t o = (size_t)row * Ee + tid * 4;
    *(uint2*)(hi + o) = *(const uint2*)hv;
    *(uint2*)(lo + o) = *(const uint2*)lv;
}

// ====== W[K][M] f32 -> Wt_hi/lo[M][K] bf16 (transpose + split, scaled) ======
__global__ __launch_bounds__(256) void convT_hl_kernel(
    const float* __restrict__ W, __nv_bfloat16* __restrict__ th,
    __nv_bfloat16* __restrict__ tl, int K, int M, float scale)
{
    __shared__ float t[32][33];
    int m0 = blockIdx.x * 32, k0 = blockIdx.y * 32;
    int tx = threadIdx.x, ty = threadIdx.y;   // (32, 8)
    #pragma unroll
    for (int j = 0; j < 4; j++)
        t[ty + j*8][tx] = W[(size_t)(k0 + ty + j*8) * M + m0 + tx];
    __syncthreads();
    #pragma unroll
    for (int j = 0; j < 4; j++) {
        int ml = ty + j*8;
        float f = t[tx][ml] * scale;
        __nv_bfloat16 hv = __float2bfloat16(f);
        __nv_bfloat16 lv = __float2bfloat16(f - __bfloat162float(hv));
        size_t o = (size_t)(m0 + ml) * K + k0 + tx;
        th[o] = hv;
        tl[o] = lv;
    }
}

// ====== V [t][E] hi/lo -> V^T [b,h][d][t] hi/lo =============================
__global__ __launch_bounds__(256) void vtrans_kernel(
    const __nv_bfloat16* __restrict__ vh, const __nv_bfloat16* __restrict__ vl,
    __nv_bfloat16* __restrict__ vth, __nv_bfloat16* __restrict__ vtl)
{
    __shared__ __nv_bfloat16 s[64][72];
    int tc = blockIdx.x, h = blockIdx.y, b = blockIdx.z;
    int tid = threadIdx.x;
    #pragma unroll
    for (int pass = 0; pass < 2; pass++) {
        const __nv_bfloat16* src = pass ? vl : vh;
        __nv_bfloat16* dst = pass ? vtl : vth;
        #pragma unroll
        for (int it = 0; it < 16; it++) {
            int idx = tid + it * 256;
            int r = idx >> 6, d = idx & 63;
            s[r][d] = src[(size_t)(b*Tt + tc*64 + r) * Ee + h*64 + d];
        }
        __syncthreads();
        #pragma unroll
        for (int it = 0; it < 16; it++) {
            int idx = tid + it * 256;
            int d = idx >> 6, c = idx & 63;
            dst[((size_t)(b*Hh + h)*64 + d) * Tt + tc*64 + c] = s[c][d];
        }
        __syncthreads();
    }
}

// ======================= HMMA split-bf16 GEMM (R11 proven config) ===========
// 128x128x32 block tile, 256 thr (8 warps 2x4, each 64x32), 2-stage cp.async.
#define T_AH 0
#define T_AL 10240
#define T_BH 20480
#define T_BL 30720
#define STAGE_B 40960
#define HG_SMEM (2 * STAGE_B)

struct QKVArgs {
    const __nv_bfloat16* bh[3];
    const __nv_bfloat16* bl[3];
    __nv_bfloat16* oh[3];
    __nv_bfloat16* ol[3];
};

// Shared mainloop body. colBlocks = number of 128-col blocks per matrix.
template<int RELU, int BIAS, int RES, int OUTHL>
__device__ __forceinline__ void hgemm_body(
    const __nv_bfloat16* Ah, const __nv_bfloat16* Al,
    const __nv_bfloat16* Bh, const __nv_bfloat16* Bl,
    const float* bias, const float* res,
    float* C, __nv_bfloat16* Chi, __nv_bfloat16* Clo,
    int K, int M, int row0, int col0, char* smem)
{
    const uint32_t sb = smem_to_u32(smem);
    const int tid = threadIdx.x;
    const int wid = tid >> 5, lid = tid & 31;
    const int wr = wid >> 2, wc = wid & 3;

    const __nv_bfloat16* src[4] = {
        Ah + (size_t)row0 * K, Al + (size_t)row0 * K,
        Bh + (size_t)col0 * K, Bl + (size_t)col0 * K };

    const int ldr0 = tid >> 2, ldseg = (tid & 3);
    const uint32_t mrow = (uint32_t)(lid & 15);
    const uint32_t mcol = (uint32_t)(lid >> 4);
    const uint32_t aLane = (uint32_t)((wr * 64 + mrow) * 80 + mcol * 16);
    const uint32_t bLane = (uint32_t)((wc * 32 + mrow) * 80 + mcol * 16);

    float acc[4][4][4] = {};
    const int nchunk = K >> 5;

    auto issue = [&](int c, int stg) {
        const size_t k0 = (size_t)c * 32;
        #pragma unroll
        for (int t = 0; t < 4; t++) {
            const __nv_bfloat16* s = src[t] + k0;
            uint32_t dst = sb + stg * STAGE_B + t * 10240;
            #pragma unroll
            for (int i = 0; i < 2; i++) {
                int r = ldr0 + i * 64;
                cp_async16(dst + (uint32_t)(r * 80 + ldseg * 16),
                           s + (size_t)r * K + ldseg * 8);
            }
        }
        CP_COMMIT();
    };

    issue(0, 0);
    for (int c = 0; c < nchunk; c++) {
        if (c + 1 < nchunk) {
            issue(c + 1, (c + 1) & 1);
            CP_WAIT(1);
        } else {
            CP_WAIT(0);
        }
        __syncthreads();

        const uint32_t st = sb + (uint32_t)((c & 1) * STAGE_B);
        #pragma unroll
        for (int kk = 0; kk < 2; kk++) {
            const uint32_t ko = (uint32_t)(kk * 32);
            uint32_t ah[4][4], al[4][4], bh[2][4], bl[2][4];
            #pragma unroll
            for (int mi = 0; mi < 4; mi++) {
                ldmx4(ah[mi][0], ah[mi][1], ah[mi][2], ah[mi][3],
                      st + T_AH + aLane + (uint32_t)(mi * 1280) + ko);
                ldmx4(al[mi][0], al[mi][1], al[mi][2], al[mi][3],
                      st + T_AL + aLane + (uint32_t)(mi * 1280) + ko);
            }
            #pragma unroll
            for (int np = 0; np < 2; np++) {
                ldmx4(bh[np][0], bh[np][1], bh[np][2], bh[np][3],
                      st + T_BH + bLane + (uint32_t)(np * 1280) + ko);
                ldmx4(bl[np][0], bl[np][1], bl[np][2], bl[np][3],
                      st + T_BL + bLane + (uint32_t)(np * 1280) + ko);
            }
            #pragma unroll
            for (int mi = 0; mi < 4; mi++) {
                #pragma unroll
                for (int nj = 0; nj < 4; nj++) {
                    uint32_t h0 = bh[nj >> 1][nj & 1], h1 = bh[nj >> 1][(nj & 1) + 2];
                    uint32_t l0 = bl[nj >> 1][nj & 1], l1 = bl[nj >> 1][(nj & 1) + 2];
                    float* cc = acc[mi][nj];
                    mma16816(cc, ah[mi][0], ah[mi][1], ah[mi][2], ah[mi][3], h0, h1);
                    mma16816(cc, ah[mi][0], ah[mi][1], ah[mi][2], ah[mi][3], l0, l1);
                    mma16816(cc, al[mi][0], al[mi][1], al[mi][2], al[mi][3], h0, h1);
                }
            }
        }
        __syncthreads();
    }

    const int l4 = lid >> 2, l2 = (lid & 3) * 2;
    #pragma unroll
    for (int mi = 0; mi < 4; mi++) {
        const int r = row0 + wr * 64 + mi * 16 + l4;
        #pragma unroll
        for (int nj = 0; nj < 4; nj++) {
            const int cgl = col0 + wc * 32 + nj * 8 + l2;
            float b0 = 0.f, b1 = 0.f;
            if (BIAS) { b0 = bias[cgl]; b1 = bias[cgl + 1]; }
            float v0 = acc[mi][nj][0] + b0, v1 = acc[mi][nj][1] + b1;
            float v2 = acc[mi][nj][2] + b0, v3 = acc[mi][nj][3] + b1;
            if (RELU) {
                v0 = fmaxf(v0, 0.f); v1 = fmaxf(v1, 0.f);
                v2 = fmaxf(v2, 0.f); v3 = fmaxf(v3, 0.f);
            }
            if (RES) {
                const float* r0p = res + (size_t)r * M + cgl;
                const float* r1p = res + (size_t)(r + 8) * M + cgl;
                v0 += r0p[0]; v1 += r0p[1];
                v2 += r1p[0]; v3 += r1p[1];
            }
            if (OUTHL) {
                *(uint32_t*)(Chi + (size_t)r * M + cgl)       = pk2(v0, v1);
                *(uint32_t*)(Clo + (size_t)r * M + cgl)       = pk2(blo(v0), blo(v1));
                *(uint32_t*)(Chi + (size_t)(r + 8) * M + cgl) = pk2(v2, v3);
                *(uint32_t*)(Clo + (size_t)(r + 8) * M + cgl) = pk2(blo(v2), blo(v3));
            } else {
                float2 o0 = {v0, v1}, o1 = {v2, v3};
                *(float2*)(C + (size_t)r * M + cgl) = o0;
                *(float2*)(C + (size_t)(r + 8) * M + cgl) = o1;
            }
        }
    }
}

template<int RELU, int BIAS, int RES, int OUTHL>
__global__ __launch_bounds__(256, 1) void hgemm_kernel(
    const __nv_bfloat16* __restrict__ Ah, const __nv_bfloat16* __restrict__ Al,
    const __nv_bfloat16* __restrict__ Bh, const __nv_bfloat16* __restrict__ Bl,
    const float* __restrict__ bias, const float* __restrict__ res,
    float* __restrict__ C, __nv_bfloat16* __restrict__ Chi,
    __nv_bfloat16* __restrict__ Clo, int K, int M)
{
    extern __shared__ char smem[];
    hgemm_body<RELU, BIAS, RES, OUTHL>(
        Ah, Al, Bh, Bl, bias, res, C, Chi, Clo, K, M,
        blockIdx.y * 128, blockIdx.x * 128, smem);
}

// Fused QKV: one launch, 3x the col-blocks; blockIdx.x selects matrix.
__global__ __launch_bounds__(256, 1) void hgemm_qkv_kernel(
    const __nv_bfloat16* __restrict__ Ah, const __nv_bfloat16* __restrict__ Al,
    QKVArgs args, int K, int M)
{
    extern __shared__ char smem[];
    const int which = blockIdx.x >> 3;
    const int col0 = (blockIdx.x & 7) * 128;
    hgemm_body<0, 0, 0, 1>(
        Ah, Al, args.bh[which], args.bl[which], nullptr, nullptr,
        nullptr, args.oh[which], args.ol[which], K, M,
        blockIdx.y * 128, col0, smem);
}

// ======================= HMMA flash attention (split bf16) ==================
#define FQH 0
#define FQL 9216
#define FKH 18432
#define FKL 27648
#define FVH 36864
#define FVL 46080
#define FL_SMEM 55296

__global__ __launch_bounds__(128) void flash_mma_kernel(
    const __nv_bfloat16* __restrict__ qh, const __nv_bfloat16* __restrict__ ql,
    const __nv_bfloat16* __restrict__ kh, const __nv_bfloat16* __restrict__ kl,
    const __nv_bfloat16* __restrict__ vth, const __nv_bfloat16* __restrict__ vtl,
    __nv_bfloat16* __restrict__ atth, __nv_bfloat16* __restrict__ attl)
{
    extern __shared__ char smf[];
    const uint32_t sb = smem_to_u32(smf);
    const int qt = blockIdx.x, h = blockIdx.y, b = blockIdx.z;
    const int tid = threadIdx.x, wid = tid >> 5, lid = tid & 31;

    const int lr = tid >> 1, lcb = (tid & 1) * 4;
    auto ldtile = [&](uint32_t off, const __nv_bfloat16* g, int gs) {
        #pragma unroll
        for (int i = 0; i < 4; i++)
            cp_async16(sb + off + (uint32_t)(lr * 144 + (lcb + i) * 16),
                       g + (size_t)lr * gs + (lcb + i) * 8);
    };

    const __nv_bfloat16* qsh = qh + ((size_t)(b*Tt + qt*64)) * Ee + h*64;
    const __nv_bfloat16* qsl = ql + ((size_t)(b*Tt + qt*64)) * Ee + h*64;
    const __nv_bfloat16* vbh = vth + ((size_t)(b*Hh + h) * 64) * Tt;
    const __nv_bfloat16* vbl = vtl + ((size_t)(b*Hh + h) * 64) * Tt;

    ldtile(FQH, qsh, Ee); ldtile(FQL, qsl, Ee);
    ldtile(FKH, kh + ((size_t)(b*Tt)) * Ee + h*64, Ee);
    ldtile(FKL, kl + ((size_t)(b*Tt)) * Ee + h*64, Ee);
    ldtile(FVH, vbh, Tt); ldtile(FVL, vbl, Tt);
    CP_COMMIT(); CP_WAIT(0);
    __syncthreads();

    const uint32_t arow = (uint32_t)(wid * 16 + (lid & 15));
    const uint32_t fcol = (uint32_t)((lid >> 4) * 16);
    uint32_t qfh[4][4], qfl[4][4];
    #pragma unroll
    for (int c = 0; c < 4; c++) {
        ldmx4(qfh[c][0], qfh[c][1], qfh[c][2], qfh[c][3],
              sb + FQH + arow * 144 + (uint32_t)(c * 32) + fcol);
        ldmx4(qfl[c][0], qfl[c][1], qfl[c][2], qfl[c][3],
              sb + FQL + arow * 144 + (uint32_t)(c * 32) + fcol);
    }

    const uint32_t brow = (uint32_t)(lid & 15);
    float oacc[8][4] = {};
    float m0 = -INFINITY, m1 = -INFINITY, l0 = 0.f, l1 = 0.f;

    const int rl0 = wid * 16 + (lid >> 2);
    const int cl0 = (lid & 3) * 2;

    for (int kt = 0; kt <= qt; kt++) {
        float sacc[8][4] = {};
        #pragma unroll
        for (int c = 0; c < 4; c++) {
            uint32_t bh_[4][4], bl_[4][4];
            #pragma unroll
            for (int np = 0; np < 4; np++) {
                ldmx4(bh_[np][0], bh_[np][1], bh_[np][2], bh_[np][3],
                      sb + FKH + (uint32_t)((np*16 + brow) * 144 + c*32) + fcol);
                ldmx4(bl_[np][0], bl_[np][1], bl_[np][2], bl_[np][3],
                      sb + FKL + (uint32_t)((np*16 + brow) * 144 + c*32) + fcol);
            }
            #pragma unroll
            for (int np = 0; np < 4; np++) {
                #pragma unroll
                for (int hf = 0; hf < 2; hf++) {
                    uint32_t H0 = bh_[np][hf], H1 = bh_[np][hf + 2];
                    uint32_t L0 = bl_[np][hf], L1 = bl_[np][hf + 2];
                    float* cc = sacc[2*np + hf];
                    mma16816(cc, qfh[c][0], qfh[c][1], qfh[c][2], qfh[c][3], H0, H1);
                    mma16816(cc, qfh[c][0], qfh[c][1], qfh[c][2], qfh[c][3], L0, L1);
                    mma16816(cc, qfl[c][0], qfl[c][1], qfl[c][2], qfl[c][3], H0, H1);
                }
            }
        }

        if (kt == qt) {
            #pragma unroll
            for (int j = 0; j < 8; j++) {
                int cb = j * 8 + cl0;
                #pragma unroll
                for (int e = 0; e < 4; e++) {
                    int cc = cb + (e & 1);
                    int rr = rl0 + ((e >= 2) ? 8 : 0);
                    if (cc > rr) sacc[j][e] = -INFINITY;
                }
            }
        }

        float mx0 = -INFINITY, mx1 = -INFINITY;
        #pragma unroll
        for (int j = 0; j < 8; j++) {
            mx0 = fmaxf(mx0, fmaxf(sacc[j][0], sacc[j][1]));
            mx1 = fmaxf(mx1, fmaxf(sacc[j][2], sacc[j][3]));
        }
        mx0 = fmaxf(mx0, __shfl_xor_sync(0xffffffffu, mx0, 1));
        mx0 = fmaxf(mx0, __shfl_xor_sync(0xffffffffu, mx0, 2));
        mx1 = fmaxf(mx1, __shfl_xor_sync(0xffffffffu, mx1, 1));
        mx1 = fmaxf(mx1, __shfl_xor_sync(0xffffffffu, mx1, 2));
        float mn0 = fmaxf(m0, mx0), mn1 = fmaxf(m1, mx1);
        float cr0 = __expf(m0 - mn0), cr1 = __expf(m1 - mn1);
        m0 = mn0; m1 = mn1;
        float s0 = 0.f, s1 = 0.f;
        #pragma unroll
        for (int j = 0; j < 8; j++) {
            sacc[j][0] = __expf(sacc[j][0] - mn0);
            sacc[j][1] = __expf(sacc[j][1] - mn0);
            sacc[j][2] = __expf(sacc[j][2] - mn1);
            sacc[j][3] = __expf(sacc[j][3] - mn1);
            s0 += sacc[j][0] + sacc[j][1];
            s1 += sacc[j][2] + sacc[j][3];
        }
        s0 += __shfl_xor_sync(0xffffffffu, s0, 1);
        s0 += __shfl_xor_sync(0xffffffffu, s0, 2);
        s1 += __shfl_xor_sync(0xffffffffu, s1, 1);
        s1 += __shfl_xor_sync(0xffffffffu, s1, 2);
        l0 = l0 * cr0 + s0;
        l1 = l1 * cr1 + s1;
        #pragma unroll
        for (int j = 0; j < 8; j++) {
            oacc[j][0] *= cr0; oacc[j][1] *= cr0;
            oacc[j][2] *= cr1; oacc[j][3] *= cr1;
        }

        uint32_t pfh[4][4], pfl[4][4];
        #pragma unroll
        for (int kc = 0; kc < 4; kc++) {
            const float* pa = sacc[2*kc];
            const float* pb = sacc[2*kc + 1];
            pfh[kc][0] = pk2(pa[0], pa[1]);
            pfh[kc][1] = pk2(pa[2], pa[3]);
            pfh[kc][2] = pk2(pb[0], pb[1]);
            pfh[kc][3] = pk2(pb[2], pb[3]);
            pfl[kc][0] = pk2(blo(pa[0]), blo(pa[1]));
            pfl[kc][1] = pk2(blo(pa[2]), blo(pa[3]));
            pfl[kc][2] = pk2(blo(pb[0]), blo(pb[1]));
            pfl[kc][3] = pk2(blo(pb[2]), blo(pb[3]));
        }

        #pragma unroll
        for (int kc = 0; kc < 4; kc++) {
            uint32_t vh_[4][4], vl_[4][4];
            #pragma unroll
            for (int np = 0; np < 4; np++) {
                ldmx4(vh_[np][0], vh_[np][1], vh_[np][2], vh_[np][3],
                      sb + FVH + (uint32_t)((np*16 + brow) * 144 + kc*32) + fcol);
                ldmx4(vl_[np][0], vl_[np][1], vl_[np][2], vl_[np][3],
                      sb + FVL + (uint32_t)((np*16 + brow) * 144 + kc*32) + fcol);
            }
            #pragma unroll
            for (int np = 0; np < 4; np++) {
                #pragma unroll
                for (int hf = 0; hf < 2; hf++) {
                    uint32_t H0 = vh_[np][hf], H1 = vh_[np][hf + 2];
                    uint32_t L0 = vl_[np][hf], L1 = vl_[np][hf + 2];
                    float* cc = oacc[2*np + hf];
                    mma16816(cc, pfh[kc][0], pfh[kc][1], pfh[kc][2], pfh[kc][3], H0, H1);
                    mma16816(cc, pfh[kc][0], pfh[kc][1], pfh[kc][2], pfh[kc][3], L0, L1);
                    mma16816(cc, pfl[kc][0], pfl[kc][1], pfl[kc][2], pfl[kc][3], H0, H1);
                }
            }
        }

        if (kt < qt) {
            __syncthreads();
            ldtile(FKH, kh + ((size_t)(b*Tt + (kt+1)*64)) * Ee + h*64, Ee);
            ldtile(FKL, kl + ((size_t)(b*Tt + (kt+1)*64)) * Ee + h*64, Ee);
            ldtile(FVH, vbh + (kt+1)*64, Tt);
            ldtile(FVL, vbl + (kt+1)*64, Tt);
            CP_COMMIT(); CP_WAIT(0);
            __syncthreads();
        }
    }

    float i0 = 1.f / l0, i1 = 1.f / l1;
    const size_t r0 = (size_t)(b*Tt + qt*64 + rl0);
    #pragma unroll
    for (int j = 0; j < 8; j++) {
        int d0 = h*64 + j*8 + cl0;
        float o0 = oacc[j][0] * i0, o1 = oacc[j][1] * i0;
        float o2 = oacc[j][2] * i1, o3 = oacc[j][3] * i1;
        *(uint32_t*)(atth + r0 * Ee + d0)       = pk2(o0, o1);
        *(uint32_t*)(attl + r0 * Ee + d0)       = pk2(blo(o0), blo(o1));
        *(uint32_t*)(atth + (r0 + 8) * Ee + d0) = pk2(o2, o3);
        *(uint32_t*)(attl + (r0 + 8) * Ee + d0) = pk2(blo(o2), blo(o3));
    }
}

// ======================= orchestration ======================================
extern "C" void kernel_launch(void* const* d_in, const int* in_sizes, int n_in,
                              void* d_out, int out_size)
{
    (void)in_sizes; (void)n_in; (void)out_size;
    const float* x     = (const float*)d_in[0];
    const float* ln1_g = (const float*)d_in[1];
    const float* ln1_b = (const float*)d_in[2];
    const float* Wq    = (const float*)d_in[3];
    const float* Wk    = (const float*)d_in[4];
    const float* Wv    = (const float*)d_in[5];
    const float* Wo    = (const float*)d_in[6];
    const float* bo    = (const float*)d_in[7];
    const float* ln2_g = (const float*)d_in[8];
    const float* ln2_b = (const float*)d_in[9];
    const float* W1    = (const float*)d_in[10];
    const float* b1    = (const float*)d_in[11];
    const float* W2    = (const float*)d_in[12];
    const float* b2    = (const float*)d_in[13];
    float* out = (float*)d_out;

    float* x1;
    cudaGetSymbolAddress((void**)&x1, g_x1);

    __nv_bfloat16 *wqh,*wql,*wkh,*wkl,*wvh,*wvl,*woh,*wol,*w1h,*w1l,*w2h,*w2l;
    __nv_bfloat16 *ah,*al,*qh,*ql,*kh,*kl,*vh,*vl,*vth,*vtl,*atth,*attl,*hh,*hl;
    cudaGetSymbolAddress((void**)&wqh, g_wqh); cudaGetSymbolAddress((void**)&wql, g_wql);
    cudaGetSymbolAddress((void**)&wkh, g_wkh); cudaGetSymbolAddress((void**)&wkl, g_wkl);
    cudaGetSymbolAddress((void**)&wvh, g_wvh); cudaGetSymbolAddress((void**)&wvl, g_wvl);
    cudaGetSymbolAddress((void**)&woh, g_woh); cudaGetSymbolAddress((void**)&wol, g_wol);
    cudaGetSymbolAddress((void**)&w1h, g_w1h); cudaGetSymbolAddress((void**)&w1l, g_w1l);
    cudaGetSymbolAddress((void**)&w2h, g_w2h); cudaGetSymbolAddress((void**)&w2l, g_w2l);
    cudaGetSymbolAddress((void**)&ah,  g_ah);  cudaGetSymbolAddress((void**)&al,  g_al);
    cudaGetSymbolAddress((void**)&qh,  g_qh);  cudaGetSymbolAddress((void**)&ql,  g_ql);
    cudaGetSymbolAddress((void**)&kh,  g_kh);  cudaGetSymbolAddress((void**)&kl,  g_kl);
    cudaGetSymbolAddress((void**)&vh,  g_vh);  cudaGetSymbolAddress((void**)&vl,  g_vl);
    cudaGetSymbolAddress((void**)&vth, g_vth); cudaGetSymbolAddress((void**)&vtl, g_vtl);
    cudaGetSymbolAddress((void**)&atth,g_atth);cudaGetSymbolAddress((void**)&attl,g_attl);
    cudaGetSymbolAddress((void**)&hh,  g_hh);  cudaGetSymbolAddress((void**)&hl,  g_hl);

    cudaFuncSetAttribute(hgemm_qkv_kernel,      cudaFuncAttributeMaxDynamicSharedMemorySize, HG_SMEM);
    cudaFuncSetAttribute(hgemm_kernel<1,1,0,1>, cudaFuncAttributeMaxDynamicSharedMemorySize, HG_SMEM);
    cudaFuncSetAttribute(hgemm_kernel<0,1,1,0>, cudaFuncAttributeMaxDynamicSharedMemorySize, HG_SMEM);
    cudaFuncSetAttribute(flash_mma_kernel, cudaFuncAttributeMaxDynamicSharedMemorySize, FL_SMEM);

    dim3 tb(32, 8);
    dim3 gE(8, 32);
    dim3 gQKV(24, 32);
    dim3 gF(32, 32);

    // weight conversions (Wq pre-scaled by 1/sqrt(D))
    convT_hl_kernel<<<dim3(32, 32),  tb>>>(Wq, wqh, wql, Ee, Ee, 0.125f);
    convT_hl_kernel<<<dim3(32, 32),  tb>>>(Wk, wkh, wkl, Ee, Ee, 1.f);
    convT_hl_kernel<<<dim3(32, 32),  tb>>>(Wv, wvh, wvl, Ee, Ee, 1.f);
    convT_hl_kernel<<<dim3(32, 32),  tb>>>(Wo, woh, wol, Ee, Ee, 1.f);
    convT_hl_kernel<<<dim3(128, 32), tb>>>(W1, w1h, w1l, Ee, FF, 1.f);
    convT_hl_kernel<<<dim3(32, 128), tb>>>(W2, w2h, w2l, FF, Ee, 1.f);

    // 1) LN1 -> bf16 hi/lo
    ln_hl_kernel<<<Nn, 256>>>(x, ln1_g, ln1_b, ah, al);
    // 2-4) fused q/k/v (one launch, 768 CTAs)
    QKVArgs qa;
    qa.bh[0] = wqh; qa.bl[0] = wql; qa.oh[0] = qh; qa.ol[0] = ql;
    qa.bh[1] = wkh; qa.bl[1] = wkl; qa.oh[1] = kh; qa.ol[1] = kl;
    qa.bh[2] = wvh; qa.bl[2] = wvl; qa.oh[2] = vh; qa.ol[2] = vl;
    hgemm_qkv_kernel<<<gQKV, 256, HG_SMEM>>>(ah, al, qa, Ee, Ee);
    // 5) V transpose + flash attention
    vtrans_kernel<<<dim3(Tt/64, Hh, Bb), 256>>>(vh, vl, vth, vtl);
    flash_mma_kernel<<<dim3(Tt/64, Hh, Bb), 128, FL_SMEM>>>(qh, ql, kh, kl, vth, vtl, atth, attl);
    // 6) x1 = x + att @ Wo + bo
    hgemm_kernel<0,1,1,0><<<gE, 256, HG_SMEM>>>(atth, attl, woh, wol, bo, x, x1, nullptr, nullptr, Ee, Ee);
    // 7) LN2 -> bf16 hi/lo
    ln_hl_kernel<<<Nn, 256>>>(x1, ln2_g, ln2_b, hh, hl);
    // 8) ff = relu(h @ W1 + b1)  (bf16 hi/lo output)
    hgemm_kernel<1,1,0,1><<<gF, 256, HG_SMEM>>>(hh, hl, w1h, w1l, b1, nullptr, nullptr, ah, al, Ee, FF);
    // 9) out = x1 + ff @ W2 + b2
    hgemm_kernel<0,1,1,0><<<gE, 256, HG_SMEM>>>(ah, al, w2h, w2l, b2, x1, out, nullptr, nullptr, FF, Ee);
}

// round 17
// speedup vs baseline: 1.1781x; 1.0034x over previous
#include <cuda_runtime.h>
#include <cuda_bf16.h>
#include <cstdint>
#include <math.h>

#define Bb 2
#define Tt 2048
#define Ee 1024
#define Hh 16
#define Dd 64
#define Nn (Bb*Tt)      /* 4096 rows */
#define FF 4096
#define LN_EPS 1e-5f

// ======================= scratch (__device__ globals) =======================
__device__ float g_x1[Nn*Ee];

// bf16 split weights, transposed to [M_out][K] (K-major rows)
__device__ __nv_bfloat16 g_wqh[Ee*Ee], g_wql[Ee*Ee];
__device__ __nv_bfloat16 g_wkh[Ee*Ee], g_wkl[Ee*Ee];
__device__ __nv_bfloat16 g_wvh[Ee*Ee], g_wvl[Ee*Ee];
__device__ __nv_bfloat16 g_woh[Ee*Ee], g_wol[Ee*Ee];
__device__ __nv_bfloat16 g_w1h[(size_t)Ee*FF], g_w1l[(size_t)Ee*FF];
__device__ __nv_bfloat16 g_w2h[(size_t)FF*Ee], g_w2l[(size_t)FF*Ee];
// bf16 split activations
__device__ __nv_bfloat16 g_ah[(size_t)Nn*FF], g_al[(size_t)Nn*FF]; // LN1 out, later FF out
__device__ __nv_bfloat16 g_qh[Nn*Ee],  g_ql[Nn*Ee];
__device__ __nv_bfloat16 g_kh[Nn*Ee],  g_kl[Nn*Ee];
__device__ __nv_bfloat16 g_vh[Nn*Ee],  g_vl[Nn*Ee];
__device__ __nv_bfloat16 g_vth[Nn*Ee], g_vtl[Nn*Ee];   // V^T: [b,h][d][t]
__device__ __nv_bfloat16 g_atth[Nn*Ee], g_attl[Nn*Ee];
__device__ __nv_bfloat16 g_hh[Nn*Ee],  g_hl[Nn*Ee];    // LN2 out

// ======================= PTX helpers (baseline compute_103 only) ============
__device__ __forceinline__ uint32_t smem_to_u32(const void* p) {
    uint32_t a;
    asm("{ .reg .u64 t; cvta.to.shared.u64 t, %1; cvt.u32.u64 %0, t; }"
        : "=r"(a) : "l"(p));
    return a;
}
__device__ __forceinline__ void cp_async16(uint32_t dst, const void* src) {
    asm volatile("cp.async.cg.shared.global [%0], [%1], 16;"
                 :: "r"(dst), "l"(src) : "memory");
}
#define CP_COMMIT() asm volatile("cp.async.commit_group;" ::: "memory")
#define CP_WAIT(n)  asm volatile("cp.async.wait_group %0;" :: "n"(n) : "memory")

__device__ __forceinline__ void ldmx4(uint32_t& r0, uint32_t& r1,
                                      uint32_t& r2, uint32_t& r3, uint32_t a) {
    asm volatile("ldmatrix.sync.aligned.m8n8.x4.shared.b16 {%0,%1,%2,%3}, [%4];"
                 : "=r"(r0), "=r"(r1), "=r"(r2), "=r"(r3) : "r"(a));
}
__device__ __forceinline__ void mma16816(float* c, uint32_t a0, uint32_t a1,
                                         uint32_t a2, uint32_t a3,
                                         uint32_t b0, uint32_t b1) {
    asm volatile(
        "mma.sync.aligned.m16n8k16.row.col.f32.bf16.bf16.f32 "
        "{%0,%1,%2,%3}, {%4,%5,%6,%7}, {%8,%9}, {%0,%1,%2,%3};"
        : "+f"(c[0]), "+f"(c[1]), "+f"(c[2]), "+f"(c[3])
        : "r"(a0), "r"(a1), "r"(a2), "r"(a3), "r"(b0), "r"(b1));
}
__device__ __forceinline__ uint32_t pk2(float a, float b) {
    __nv_bfloat16 ha = __float2bfloat16(a), hb = __float2bfloat16(b);
    uint16_t ua = *(uint16_t*)&ha, ub = *(uint16_t*)&hb;
    return (uint32_t)ua | ((uint32_t)ub << 16);
}
__device__ __forceinline__ float blo(float a) {  // residual after bf16 round
    __nv_bfloat16 h = __float2bfloat16(a);
    return a - __bfloat162float(h);
}

// ======================= LayerNorm -> bf16 hi/lo ============================
__global__ __launch_bounds__(256) void ln_hl_kernel(
    const float* __restrict__ x, const float* __restrict__ gamma,
    const float* __restrict__ beta, __nv_bfloat16* __restrict__ hi,
    __nv_bfloat16* __restrict__ lo)
{
    int row = blockIdx.x;
    int tid = threadIdx.x;
    const float4* xp = (const float4*)(x + (size_t)row * Ee);
    float4 v = xp[tid];
    float s  = v.x + v.y + v.z + v.w;
    float sq = v.x*v.x + v.y*v.y + v.z*v.z + v.w*v.w;
    #pragma unroll
    for (int m = 16; m >= 1; m >>= 1) {
        s  += __shfl_xor_sync(0xffffffffu, s,  m);
        sq += __shfl_xor_sync(0xffffffffu, sq, m);
    }
    __shared__ float sh[16];
    int w = tid >> 5, l = tid & 31;
    if (l == 0) { sh[w] = s; sh[8 + w] = sq; }
    __syncthreads();
    if (tid < 32) {
        s  = (l < 8) ? sh[l]     : 0.f;
        sq = (l < 8) ? sh[8 + l] : 0.f;
        #pragma unroll
        for (int m = 4; m >= 1; m >>= 1) {
            s  += __shfl_xor_sync(0xffffffffu, s,  m);
            sq += __shfl_xor_sync(0xffffffffu, sq, m);
        }
        if (l == 0) { sh[0] = s; sh[8] = sq; }
    }
    __syncthreads();
    float mu  = sh[0] * (1.0f/Ee);
    float var = sh[8] * (1.0f/Ee) - mu*mu;
    float inv = rsqrtf(var + LN_EPS);
    float4 gv = ((const float4*)gamma)[tid];
    float4 bv = ((const float4*)beta)[tid];
    float f[4];
    f[0] = (v.x - mu)*inv*gv.x + bv.x;
    f[1] = (v.y - mu)*inv*gv.y + bv.y;
    f[2] = (v.z - mu)*inv*gv.z + bv.z;
    f[3] = (v.w - mu)*inv*gv.w + bv.w;
    __nv_bfloat16 hv[4], lv[4];
    #pragma unroll
    for (int j = 0; j < 4; j++) {
        hv[j] = __float2bfloat16(f[j]);
        lv[j] = __float2bfloat16(f[j] - __bfloat162float(hv[j]));
    }
    size_t o = (size_t)row * Ee + tid * 4;
    *(uint2*)(hi + o) = *(const uint2*)hv;
    *(uint2*)(lo + o) = *(const uint2*)lv;
}

// ====== W[K][M] f32 -> Wt_hi/lo[M][K] bf16 (transpose + split, scaled) ======
__global__ __launch_bounds__(256) void convT_hl_kernel(
    const float* __restrict__ W, __nv_bfloat16* __restrict__ th,
    __nv_bfloat16* __restrict__ tl, int K, int M, float scale)
{
    __shared__ float t[32][33];
    int m0 = blockIdx.x * 32, k0 = blockIdx.y * 32;
    int tx = threadIdx.x, ty = threadIdx.y;   // (32, 8)
    #pragma unroll
    for (int j = 0; j < 4; j++)
        t[ty + j*8][tx] = W[(size_t)(k0 + ty + j*8) * M + m0 + tx];
    __syncthreads();
    #pragma unroll
    for (int j = 0; j < 4; j++) {
        int ml = ty + j*8;
        float f = t[tx][ml] * scale;
        __nv_bfloat16 hv = __float2bfloat16(f);
        __nv_bfloat16 lv = __float2bfloat16(f - __bfloat162float(hv));
        size_t o = (size_t)(m0 + ml) * K + k0 + tx;
        th[o] = hv;
        tl[o] = lv;
    }
}

// ====== V [t][E] hi/lo -> V^T [b,h][d][t] hi/lo =============================
__global__ __launch_bounds__(256) void vtrans_kernel(
    const __nv_bfloat16* __restrict__ vh, const __nv_bfloat16* __restrict__ vl,
    __nv_bfloat16* __restrict__ vth, __nv_bfloat16* __restrict__ vtl)
{
    __shared__ __nv_bfloat16 s[64][72];
    int tc = blockIdx.x, h = blockIdx.y, b = blockIdx.z;
    int tid = threadIdx.x;
    #pragma unroll
    for (int pass = 0; pass < 2; pass++) {
        const __nv_bfloat16* src = pass ? vl : vh;
        __nv_bfloat16* dst = pass ? vtl : vth;
        #pragma unroll
        for (int it = 0; it < 16; it++) {
            int idx = tid + it * 256;
            int r = idx >> 6, d = idx & 63;
            s[r][d] = src[(size_t)(b*Tt + tc*64 + r) * Ee + h*64 + d];
        }
        __syncthreads();
        #pragma unroll
        for (int it = 0; it < 16; it++) {
            int idx = tid + it * 256;
            int d = idx >> 6, c = idx & 63;
            dst[((size_t)(b*Hh + h)*64 + d) * Tt + tc*64 + c] = s[c][d];
        }
        __syncthreads();
    }
}

// ======================= HMMA split-bf16 GEMM ===============================
// 128x128x32 block tile, 256 thr (8 warps 2x4, each 64x32).
// 3-stage cp.async pipeline, ONE __syncthreads per chunk, fragments upfront.
#define T_AH 0
#define T_AL 10240
#define T_BH 20480
#define T_BL 30720
#define STAGE_B 40960
#define HG_SMEM (3 * STAGE_B)

struct QKVArgs {
    const __nv_bfloat16* bh[3];
    const __nv_bfloat16* bl[3];
    __nv_bfloat16* oh[3];
    __nv_bfloat16* ol[3];
};

template<int RELU, int BIAS, int RES, int OUTHL>
__device__ __forceinline__ void hgemm_body(
    const __nv_bfloat16* Ah, const __nv_bfloat16* Al,
    const __nv_bfloat16* Bh, const __nv_bfloat16* Bl,
    const float* bias, const float* res,
    float* C, __nv_bfloat16* Chi, __nv_bfloat16* Clo,
    int K, int M, int row0, int col0, char* smem)
{
    const uint32_t sb = smem_to_u32(smem);
    const int tid = threadIdx.x;
    const int wid = tid >> 5, lid = tid & 31;
    const int wr = wid >> 2, wc = wid & 3;

    const __nv_bfloat16* src[4] = {
        Ah + (size_t)row0 * K, Al + (size_t)row0 * K,
        Bh + (size_t)col0 * K, Bl + (size_t)col0 * K };

    const int ldr0 = tid >> 2, ldseg = (tid & 3);
    const uint32_t mrow = (uint32_t)(lid & 15);
    const uint32_t mcol = (uint32_t)(lid >> 4);
    const uint32_t aLane = (uint32_t)((wr * 64 + mrow) * 80 + mcol * 16);
    const uint32_t bLane = (uint32_t)((wc * 32 + mrow) * 80 + mcol * 16);

    float acc[4][4][4] = {};
    const int nchunk = K >> 5;

    auto issue = [&](int c, int stg) {
        const size_t k0 = (size_t)c * 32;
        #pragma unroll
        for (int t = 0; t < 4; t++) {
            const __nv_bfloat16* s = src[t] + k0;
            uint32_t dst = sb + (uint32_t)(stg * STAGE_B) + t * 10240;
            #pragma unroll
            for (int i = 0; i < 2; i++) {
                int r = ldr0 + i * 64;
                cp_async16(dst + (uint32_t)(r * 80 + ldseg * 16),
                           s + (size_t)r * K + ldseg * 8);
            }
        }
        CP_COMMIT();
    };

    // prologue: 2 chunks in flight
    issue(0, 0);
    if (nchunk > 1) issue(1, 1);

    int stg = 0, stg2 = 2;   // stg = stage of chunk c; stg2 = stage of chunk c+2
    for (int c = 0; c < nchunk; c++) {
        if (c == nchunk - 1) { CP_WAIT(0); } else { CP_WAIT(1); }
        __syncthreads();
        if (c + 2 < nchunk) issue(c + 2, stg2);

        const uint32_t st = sb + (uint32_t)(stg * STAGE_B);
        // load ALL fragments for both kk upfront (24 ldmx4)
        uint32_t ah[2][4][4], al[2][4][4], bh[2][2][4], bl[2][2][4];
        #pragma unroll
        for (int kk = 0; kk < 2; kk++) {
            const uint32_t ko = (uint32_t)(kk * 32);
            #pragma unroll
            for (int mi = 0; mi < 4; mi++) {
                ldmx4(ah[kk][mi][0], ah[kk][mi][1], ah[kk][mi][2], ah[kk][mi][3],
                      st + T_AH + aLane + (uint32_t)(mi * 1280) + ko);
                ldmx4(al[kk][mi][0], al[kk][mi][1], al[kk][mi][2], al[kk][mi][3],
                      st + T_AL + aLane + (uint32_t)(mi * 1280) + ko);
            }
            #pragma unroll
            for (int np = 0; np < 2; np++) {
                ldmx4(bh[kk][np][0], bh[kk][np][1], bh[kk][np][2], bh[kk][np][3],
                      st + T_BH + bLane + (uint32_t)(np * 1280) + ko);
                ldmx4(bl[kk][np][0], bl[kk][np][1], bl[kk][np][2], bl[kk][np][3],
                      st + T_BL + bLane + (uint32_t)(np * 1280) + ko);
            }
        }
        #pragma unroll
        for (int kk = 0; kk < 2; kk++) {
            #pragma unroll
            for (int mi = 0; mi < 4; mi++) {
                #pragma unroll
                for (int nj = 0; nj < 4; nj++) {
                    uint32_t h0 = bh[kk][nj >> 1][nj & 1], h1 = bh[kk][nj >> 1][(nj & 1) + 2];
                    uint32_t l0 = bl[kk][nj >> 1][nj & 1], l1 = bl[kk][nj >> 1][(nj & 1) + 2];
                    float* cc = acc[mi][nj];
                    mma16816(cc, ah[kk][mi][0], ah[kk][mi][1], ah[kk][mi][2], ah[kk][mi][3], h0, h1);
                    mma16816(cc, ah[kk][mi][0], ah[kk][mi][1], ah[kk][mi][2], ah[kk][mi][3], l0, l1);
                    mma16816(cc, al[kk][mi][0], al[kk][mi][1], al[kk][mi][2], al[kk][mi][3], h0, h1);
                }
            }
        }
        // rotate stages (no trailing sync needed with 3 stages)
        stg  = (stg  == 2) ? 0 : stg  + 1;
        stg2 = (stg2 == 2) ? 0 : stg2 + 1;
    }

    const int l4 = lid >> 2, l2 = (lid & 3) * 2;
    #pragma unroll
    for (int mi = 0; mi < 4; mi++) {
        const int r = row0 + wr * 64 + mi * 16 + l4;
        #pragma unroll
        for (int nj = 0; nj < 4; nj++) {
            const int cgl = col0 + wc * 32 + nj * 8 + l2;
            float b0 = 0.f, b1 = 0.f;
            if (BIAS) { b0 = bias[cgl]; b1 = bias[cgl + 1]; }
            float v0 = acc[mi][nj][0] + b0, v1 = acc[mi][nj][1] + b1;
            float v2 = acc[mi][nj][2] + b0, v3 = acc[mi][nj][3] + b1;
            if (RELU) {
                v0 = fmaxf(v0, 0.f); v1 = fmaxf(v1, 0.f);
                v2 = fmaxf(v2, 0.f); v3 = fmaxf(v3, 0.f);
            }
            if (RES) {
                const float* r0p = res + (size_t)r * M + cgl;
                const float* r1p = res + (size_t)(r + 8) * M + cgl;
                v0 += r0p[0]; v1 += r0p[1];
                v2 += r1p[0]; v3 += r1p[1];
            }
            if (OUTHL) {
                *(uint32_t*)(Chi + (size_t)r * M + cgl)       = pk2(v0, v1);
                *(uint32_t*)(Clo + (size_t)r * M + cgl)       = pk2(blo(v0), blo(v1));
                *(uint32_t*)(Chi + (size_t)(r + 8) * M + cgl) = pk2(v2, v3);
                *(uint32_t*)(Clo + (size_t)(r + 8) * M + cgl) = pk2(blo(v2), blo(v3));
            } else {
                float2 o0 = {v0, v1}, o1 = {v2, v3};
                *(float2*)(C + (size_t)r * M + cgl) = o0;
                *(float2*)(C + (size_t)(r + 8) * M + cgl) = o1;
            }
        }
    }
}

template<int RELU, int BIAS, int RES, int OUTHL>
__global__ __launch_bounds__(256, 1) void hgemm_kernel(
    const __nv_bfloat16* __restrict__ Ah, const __nv_bfloat16* __restrict__ Al,
    const __nv_bfloat16* __restrict__ Bh, const __nv_bfloat16* __restrict__ Bl,
    const float* __restrict__ bias, const float* __restrict__ res,
    float* __restrict__ C, __nv_bfloat16* __restrict__ Chi,
    __nv_bfloat16* __restrict__ Clo, int K, int M)
{
    extern __shared__ char smem[];
    hgemm_body<RELU, BIAS, RES, OUTHL>(
        Ah, Al, Bh, Bl, bias, res, C, Chi, Clo, K, M,
        blockIdx.y * 128, blockIdx.x * 128, smem);
}

// Fused QKV: one launch; blockIdx.x selects matrix.
__global__ __launch_bounds__(256, 1) void hgemm_qkv_kernel(
    const __nv_bfloat16* __restrict__ Ah, const __nv_bfloat16* __restrict__ Al,
    QKVArgs args, int K, int M)
{
    extern __shared__ char smem[];
    const int which = blockIdx.x >> 3;
    const int col0 = (blockIdx.x & 7) * 128;
    hgemm_body<0, 0, 0, 1>(
        Ah, Al, args.bh[which], args.bl[which], nullptr, nullptr,
        nullptr, args.oh[which], args.ol[which], K, M,
        blockIdx.y * 128, col0, smem);
}

// ======================= HMMA flash attention (split bf16) ==================
#define FQH 0
#define FQL 9216
#define FKH 18432
#define FKL 27648
#define FVH 36864
#define FVL 46080
#define FL_SMEM 55296

__global__ __launch_bounds__(128) void flash_mma_kernel(
    const __nv_bfloat16* __restrict__ qh, const __nv_bfloat16* __restrict__ ql,
    const __nv_bfloat16* __restrict__ kh, const __nv_bfloat16* __restrict__ kl,
    const __nv_bfloat16* __restrict__ vth, const __nv_bfloat16* __restrict__ vtl,
    __nv_bfloat16* __restrict__ atth, __nv_bfloat16* __restrict__ attl)
{
    extern __shared__ char smf[];
    const uint32_t sb = smem_to_u32(smf);
    const int qt = blockIdx.x, h = blockIdx.y, b = blockIdx.z;
    const int tid = threadIdx.x, wid = tid >> 5, lid = tid & 31;

    const int lr = tid >> 1, lcb = (tid & 1) * 4;
    auto ldtile = [&](uint32_t off, const __nv_bfloat16* g, int gs) {
        #pragma unroll
        for (int i = 0; i < 4; i++)
            cp_async16(sb + off + (uint32_t)(lr * 144 + (lcb + i) * 16),
                       g + (size_t)lr * gs + (lcb + i) * 8);
    };

    const __nv_bfloat16* qsh = qh + ((size_t)(b*Tt + qt*64)) * Ee + h*64;
    const __nv_bfloat16* qsl = ql + ((size_t)(b*Tt + qt*64)) * Ee + h*64;
    const __nv_bfloat16* vbh = vth + ((size_t)(b*Hh + h) * 64) * Tt;
    const __nv_bfloat16* vbl = vtl + ((size_t)(b*Hh + h) * 64) * Tt;

    ldtile(FQH, qsh, Ee); ldtile(FQL, qsl, Ee);
    ldtile(FKH, kh + ((size_t)(b*Tt)) * Ee + h*64, Ee);
    ldtile(FKL, kl + ((size_t)(b*Tt)) * Ee + h*64, Ee);
    ldtile(FVH, vbh, Tt); ldtile(FVL, vbl, Tt);
    CP_COMMIT(); CP_WAIT(0);
    __syncthreads();

    const uint32_t arow = (uint32_t)(wid * 16 + (lid & 15));
    const uint32_t fcol = (uint32_t)((lid >> 4) * 16);
    uint32_t qfh[4][4], qfl[4][4];
    #pragma unroll
    for (int c = 0; c < 4; c++) {
        ldmx4(qfh[c][0], qfh[c][1], qfh[c][2], qfh[c][3],
              sb + FQH + arow * 144 + (uint32_t)(c * 32) + fcol);
        ldmx4(qfl[c][0], qfl[c][1], qfl[c][2], qfl[c][3],
              sb + FQL + arow * 144 + (uint32_t)(c * 32) + fcol);
    }

    const uint32_t brow = (uint32_t)(lid & 15);
    float oacc[8][4] = {};
    float m0 = -INFINITY, m1 = -INFINITY, l0 = 0.f, l1 = 0.f;

    const int rl0 = wid * 16 + (lid >> 2);
    const int cl0 = (lid & 3) * 2;

    for (int kt = 0; kt <= qt; kt++) {
        float sacc[8][4] = {};
        #pragma unroll
        for (int c = 0; c < 4; c++) {
            uint32_t bh_[4][4], bl_[4][4];
            #pragma unroll
            for (int np = 0; np < 4; np++) {
                ldmx4(bh_[np][0], bh_[np][1], bh_[np][2], bh_[np][3],
                      sb + FKH + (uint32_t)((np*16 + brow) * 144 + c*32) + fcol);
                ldmx4(bl_[np][0], bl_[np][1], bl_[np][2], bl_[np][3],
                      sb + FKL + (uint32_t)((np*16 + brow) * 144 + c*32) + fcol);
            }
            #pragma unroll
            for (int np = 0; np < 4; np++) {
                #pragma unroll
                for (int hf = 0; hf < 2; hf++) {
                    uint32_t H0 = bh_[np][hf], H1 = bh_[np][hf + 2];
                    uint32_t L0 = bl_[np][hf], L1 = bl_[np][hf + 2];
                    float* cc = sacc[2*np + hf];
                    mma16816(cc, qfh[c][0], qfh[c][1], qfh[c][2], qfh[c][3], H0, H1);
                    mma16816(cc, qfh[c][0], qfh[c][1], qfh[c][2], qfh[c][3], L0, L1);
                    mma16816(cc, qfl[c][0], qfl[c][1], qfl[c][2], qfl[c][3], H0, H1);
                }
            }
        }

        if (kt == qt) {
            #pragma unroll
            for (int j = 0; j < 8; j++) {
                int cb = j * 8 + cl0;
                #pragma unroll
                for (int e = 0; e < 4; e++) {
                    int cc = cb + (e & 1);
                    int rr = rl0 + ((e >= 2) ? 8 : 0);
                    if (cc > rr) sacc[j][e] = -INFINITY;
                }
            }
        }

        float mx0 = -INFINITY, mx1 = -INFINITY;
        #pragma unroll
        for (int j = 0; j < 8; j++) {
            mx0 = fmaxf(mx0, fmaxf(sacc[j][0], sacc[j][1]));
            mx1 = fmaxf(mx1, fmaxf(sacc[j][2], sacc[j][3]));
        }
        mx0 = fmaxf(mx0, __shfl_xor_sync(0xffffffffu, mx0, 1));
        mx0 = fmaxf(mx0, __shfl_xor_sync(0xffffffffu, mx0, 2));
        mx1 = fmaxf(mx1, __shfl_xor_sync(0xffffffffu, mx1, 1));
        mx1 = fmaxf(mx1, __shfl_xor_sync(0xffffffffu, mx1, 2));
        float mn0 = fmaxf(m0, mx0), mn1 = fmaxf(m1, mx1);
        float cr0 = __expf(m0 - mn0), cr1 = __expf(m1 - mn1);
        m0 = mn0; m1 = mn1;
        float s0 = 0.f, s1 = 0.f;
        #pragma unroll
        for (int j = 0; j < 8; j++) {
            sacc[j][0] = __expf(sacc[j][0] - mn0);
            sacc[j][1] = __expf(sacc[j][1] - mn0);
            sacc[j][2] = __expf(sacc[j][2] - mn1);
            sacc[j][3] = __expf(sacc[j][3] - mn1);
            s0 += sacc[j][0] + sacc[j][1];
            s1 += sacc[j][2] + sacc[j][3];
        }
        s0 += __shfl_xor_sync(0xffffffffu, s0, 1);
        s0 += __shfl_xor_sync(0xffffffffu, s0, 2);
        s1 += __shfl_xor_sync(0xffffffffu, s1, 1);
        s1 += __shfl_xor_sync(0xffffffffu, s1, 2);
        l0 = l0 * cr0 + s0;
        l1 = l1 * cr1 + s1;
        #pragma unroll
        for (int j = 0; j < 8; j++) {
            oacc[j][0] *= cr0; oacc[j][1] *= cr0;
            oacc[j][2] *= cr1; oacc[j][3] *= cr1;
        }

        uint32_t pfh[4][4], pfl[4][4];
        #pragma unroll
        for (int kc = 0; kc < 4; kc++) {
            const float* pa = sacc[2*kc];
            const float* pb = sacc[2*kc + 1];
            pfh[kc][0] = pk2(pa[0], pa[1]);
            pfh[kc][1] = pk2(pa[2], pa[3]);
            pfh[kc][2] = pk2(pb[0], pb[1]);
            pfh[kc][3] = pk2(pb[2], pb[3]);
            pfl[kc][0] = pk2(blo(pa[0]), blo(pa[1]));
            pfl[kc][1] = pk2(blo(pa[2]), blo(pa[3]));
            pfl[kc][2] = pk2(blo(pb[0]), blo(pb[1]));
            pfl[kc][3] = pk2(blo(pb[2]), blo(pb[3]));
        }

        #pragma unroll
        for (int kc = 0; kc < 4; kc++) {
            uint32_t vh_[4][4], vl_[4][4];
            #pragma unroll
            for (int np = 0; np < 4; np++) {
                ldmx4(vh_[np][0], vh_[np][1], vh_[np][2], vh_[np][3],
                      sb + FVH + (uint32_t)((np*16 + brow) * 144 + kc*32) + fcol);
                ldmx4(vl_[np][0], vl_[np][1], vl_[np][2], vl_[np][3],
                      sb + FVL + (uint32_t)((np*16 + brow) * 144 + kc*32) + fcol);
            }
            #pragma unroll
            for (int np = 0; np < 4; np++) {
                #pragma unroll
                for (int hf = 0; hf < 2; hf++) {
                    uint32_t H0 = vh_[np][hf], H1 = vh_[np][hf + 2];
                    uint32_t L0 = vl_[np][hf], L1 = vl_[np][hf + 2];
                    float* cc = oacc[2*np + hf];
                    mma16816(cc, pfh[kc][0], pfh[kc][1], pfh[kc][2], pfh[kc][3], H0, H1);
                    mma16816(cc, pfh[kc][0], pfh[kc][1], pfh[kc][2], pfh[kc][3], L0, L1);
                    mma16816(cc, pfl[kc][0], pfl[kc][1], pfl[kc][2], pfl[kc][3], H0, H1);
                }
            }
        }

        if (kt < qt) {
            __syncthreads();
            ldtile(FKH, kh + ((size_t)(b*Tt + (kt+1)*64)) * Ee + h*64, Ee);
            ldtile(FKL, kl + ((size_t)(b*Tt + (kt+1)*64)) * Ee + h*64, Ee);
            ldtile(FVH, vbh + (kt+1)*64, Tt);
            ldtile(FVL, vbl + (kt+1)*64, Tt);
            CP_COMMIT(); CP_WAIT(0);
            __syncthreads();
        }
    }

    float i0 = 1.f / l0, i1 = 1.f / l1;
    const size_t r0 = (size_t)(b*Tt + qt*64 + rl0);
    #pragma unroll
    for (int j = 0; j < 8; j++) {
        int d0 = h*64 + j*8 + cl0;
        float o0 = oacc[j][0] * i0, o1 = oacc[j][1] * i0;
        float o2 = oacc[j][2] * i1, o3 = oacc[j][3] * i1;
        *(uint32_t*)(atth + r0 * Ee + d0)       = pk2(o0, o1);
        *(uint32_t*)(attl + r0 * Ee + d0)       = pk2(blo(o0), blo(o1));
        *(uint32_t*)(atth + (r0 + 8) * Ee + d0) = pk2(o2, o3);
        *(uint32_t*)(attl + (r0 + 8) * Ee + d0) = pk2(blo(o2), blo(o3));
    }
}

// ======================= orchestration ======================================
extern "C" void kernel_launch(void* const* d_in, const int* in_sizes, int n_in,
                              void* d_out, int out_size)
{
    (void)in_sizes; (void)n_in; (void)out_size;
    const float* x     = (const float*)d_in[0];
    const float* ln1_g = (const float*)d_in[1];
    const float* ln1_b = (const float*)d_in[2];
    const float* Wq    = (const float*)d_in[3];
    const float* Wk    = (const float*)d_in[4];
    const float* Wv    = (const float*)d_in[5];
    const float* Wo    = (const float*)d_in[6];
    const float* bo    = (const float*)d_in[7];
    const float* ln2_g = (const float*)d_in[8];
    const float* ln2_b = (const float*)d_in[9];
    const float* W1    = (const float*)d_in[10];
    const float* b1    = (const float*)d_in[11];
    const float* W2    = (const float*)d_in[12];
    const float* b2    = (const float*)d_in[13];
    float* out = (float*)d_out;

    float* x1;
    cudaGetSymbolAddress((void**)&x1, g_x1);

    __nv_bfloat16 *wqh,*wql,*wkh,*wkl,*wvh,*wvl,*woh,*wol,*w1h,*w1l,*w2h,*w2l;
    __nv_bfloat16 *ah,*al,*qh,*ql,*kh,*kl,*vh,*vl,*vth,*vtl,*atth,*attl,*hh,*hl;
    cudaGetSymbolAddress((void**)&wqh, g_wqh); cudaGetSymbolAddress((void**)&wql, g_wql);
    cudaGetSymbolAddress((void**)&wkh, g_wkh); cudaGetSymbolAddress((void**)&wkl, g_wkl);
    cudaGetSymbolAddress((void**)&wvh, g_wvh); cudaGetSymbolAddress((void**)&wvl, g_wvl);
    cudaGetSymbolAddress((void**)&woh, g_woh); cudaGetSymbolAddress((void**)&wol, g_wol);
    cudaGetSymbolAddress((void**)&w1h, g_w1h); cudaGetSymbolAddress((void**)&w1l, g_w1l);
    cudaGetSymbolAddress((void**)&w2h, g_w2h); cudaGetSymbolAddress((void**)&w2l, g_w2l);
    cudaGetSymbolAddress((void**)&ah,  g_ah);  cudaGetSymbolAddress((void**)&al,  g_al);
    cudaGetSymbolAddress((void**)&qh,  g_qh);  cudaGetSymbolAddress((void**)&ql,  g_ql);
    cudaGetSymbolAddress((void**)&kh,  g_kh);  cudaGetSymbolAddress((void**)&kl,  g_kl);
    cudaGetSymbolAddress((void**)&vh,  g_vh);  cudaGetSymbolAddress((void**)&vl,  g_vl);
    cudaGetSymbolAddress((void**)&vth, g_vth); cudaGetSymbolAddress((void**)&vtl, g_vtl);
    cudaGetSymbolAddress((void**)&atth,g_atth);cudaGetSymbolAddress((void**)&attl,g_attl);
    cudaGetSymbolAddress((void**)&hh,  g_hh);  cudaGetSymbolAddress((void**)&hl,  g_hl);

    cudaFuncSetAttribute(hgemm_qkv_kernel,      cudaFuncAttributeMaxDynamicSharedMemorySize, HG_SMEM);
    cudaFuncSetAttribute(hgemm_kernel<1,1,0,1>, cudaFuncAttributeMaxDynamicSharedMemorySize, HG_SMEM);
    cudaFuncSetAttribute(hgemm_kernel<0,1,1,0>, cudaFuncAttributeMaxDynamicSharedMemorySize, HG_SMEM);
    cudaFuncSetAttribute(flash_mma_kernel, cudaFuncAttributeMaxDynamicSharedMemorySize, FL_SMEM);

    dim3 tb(32, 8);
    dim3 gE(8, 32);
    dim3 gQKV(24, 32);
    dim3 gF(32, 32);

    // Launch order arranged so launch index 5 (ncu -s 5 -c 1) == hgemm_qkv.
    convT_hl_kernel<<<dim3(32, 32),  tb>>>(Wq, wqh, wql, Ee, Ee, 0.125f);   // 0
    convT_hl_kernel<<<dim3(32, 32),  tb>>>(Wk, wkh, wkl, Ee, Ee, 1.f);      // 1
    convT_hl_kernel<<<dim3(32, 32),  tb>>>(Wv, wvh, wvl, Ee, Ee, 1.f);      // 2
    convT_hl_kernel<<<dim3(32, 32),  tb>>>(Wo, woh, wol, Ee, Ee, 1.f);      // 3
    ln_hl_kernel<<<Nn, 256>>>(x, ln1_g, ln1_b, ah, al);                     // 4

    QKVArgs qa;
    qa.bh[0] = wqh; qa.bl[0] = wql; qa.oh[0] = qh; qa.ol[0] = ql;
    qa.bh[1] = wkh; qa.bl[1] = wkl; qa.oh[1] = kh; qa.ol[1] = kl;
    qa.bh[2] = wvh; qa.bl[2] = wvl; qa.oh[2] = vh; qa.ol[2] = vl;
    hgemm_qkv_kernel<<<gQKV, 256, HG_SMEM>>>(ah, al, qa, Ee, Ee);           // 5 <- profiled

    vtrans_kernel<<<dim3(Tt/64, Hh, Bb), 256>>>(vh, vl, vth, vtl);          // 6
    flash_mma_kernel<<<dim3(Tt/64, Hh, Bb), 128, FL_SMEM>>>(qh, ql, kh, kl, vth, vtl, atth, attl); // 7
    convT_hl_kernel<<<dim3(128, 32), tb>>>(W1, w1h, w1l, Ee, FF, 1.f);      // 8
    convT_hl_kernel<<<dim3(32, 128), tb>>>(W2, w2h, w2l, FF, Ee, 1.f);      // 9
    hgemm_kernel<0,1,1,0><<<gE, 256, HG_SMEM>>>(atth, attl, woh, wol, bo, x, x1, nullptr, nullptr, Ee, Ee); // 10
    ln_hl_kernel<<<Nn, 256>>>(x1, ln2_g, ln2_b, hh, hl);                    // 11
    hgemm_kernel<1,1,0,1><<<gF, 256, HG_SMEM>>>(hh, hl, w1h, w1l, b1, nullptr, nullptr, ah, al, Ee, FF);   // 12
    hgemm_kernel<0,1,1,0><<<gE, 256, HG_SMEM>>>(ah, al, w2h, w2l, b2, x1, out, nullptr, nullptr, FF, Ee);  // 13
}